// round 1
// baseline (speedup 1.0000x reference)
#include <cuda_runtime.h>
#include <cuda_bf16.h>
#include <math.h>

#define D_MODEL 1024
#define N_HEADS 16
#define D_K     64
#define BATCH   2
#define SEQ     2048
#define SCALE   0.125f  /* 1/sqrt(64) */

// Scratch (allocation-free rule: use __device__ globals)
__device__ float g_qkv[(size_t)BATCH * SEQ * 3 * D_MODEL];  // [B,S,3D] 50 MB
__device__ float g_ctx[(size_t)BATCH * SEQ * D_MODEL];      // [B,S,D]  16 MB

// ---------------------------------------------------------------------------
// Tiled fp32 GEMM: C[M,N] = A[M,K] @ B[K,N], all row-major.
// 128x128 block tile, BK=8, 256 threads, 8x8 per-thread micro-tile.
// Requires M%128==0, N%128==0, K%8==0 (true for all our shapes).
// ---------------------------------------------------------------------------
__global__ void __launch_bounds__(256) gemm_kernel(
    const float* __restrict__ A, const float* __restrict__ Bm,
    float* __restrict__ C, int M, int N, int K)
{
    __shared__ float As[8][128];   // transposed A tile: As[k][m]
    __shared__ float Bs[8][128];

    const int tid = threadIdx.x;
    const int m0 = blockIdx.y * 128;
    const int n0 = blockIdx.x * 128;

    const int a_row = tid >> 1;            // 0..127
    const int a_col = (tid & 1) * 4;       // 0 or 4
    const int b_row = tid >> 5;            // 0..7
    const int b_col = (tid & 31) * 4;      // 0..124

    const float* Aptr = A + (size_t)(m0 + a_row) * K + a_col;
    const float* Bptr = Bm + (size_t)b_row * N + n0 + b_col;

    const int ty = tid >> 4;   // 0..15 (m dir)
    const int tx = tid & 15;   // 0..15 (n dir)

    float acc[8][8];
    #pragma unroll
    for (int i = 0; i < 8; i++)
        #pragma unroll
        for (int j = 0; j < 8; j++) acc[i][j] = 0.f;

    for (int kt = 0; kt < K; kt += 8) {
        float4 av = *(const float4*)(Aptr + kt);
        float4 bv = *(const float4*)(Bptr + (size_t)kt * N);
        As[a_col + 0][a_row] = av.x;
        As[a_col + 1][a_row] = av.y;
        As[a_col + 2][a_row] = av.z;
        As[a_col + 3][a_row] = av.w;
        *(float4*)&Bs[b_row][b_col] = bv;
        __syncthreads();

        #pragma unroll
        for (int k = 0; k < 8; k++) {
            float a[8], b[8];
            #pragma unroll
            for (int i = 0; i < 8; i++) a[i] = As[k][ty * 8 + i];
            #pragma unroll
            for (int j = 0; j < 8; j++) b[j] = Bs[k][tx * 8 + j];
            #pragma unroll
            for (int i = 0; i < 8; i++)
                #pragma unroll
                for (int j = 0; j < 8; j++)
                    acc[i][j] += a[i] * b[j];
        }
        __syncthreads();
    }

    #pragma unroll
    for (int i = 0; i < 8; i++) {
        int row = m0 + ty * 8 + i;
        float4* cp = (float4*)(C + (size_t)row * N + n0 + tx * 8);
        cp[0] = make_float4(acc[i][0], acc[i][1], acc[i][2], acc[i][3]);
        cp[1] = make_float4(acc[i][4], acc[i][5], acc[i][6], acc[i][7]);
    }
}

// ---------------------------------------------------------------------------
// Flash attention (causal), fp32. One block per (bh, q-tile of 64 rows).
// Thread t: row i = t & 63, col-group jg = t >> 6 (16 cols each).
// Q/K/V/P tiles in smem, stride 65 -> Q reads conflict-free (banks i+k),
// K/V reads warp-uniform (broadcast).
// ---------------------------------------------------------------------------
#define ATTN_SMEM_FLOATS (4 * 64 * 65 + 256)

__global__ void __launch_bounds__(256) attn_kernel(
    const float* __restrict__ qkv, float* __restrict__ ctx)
{
    extern __shared__ float sm[];
    float* Qs  = sm;                 // 64*65
    float* Ks  = Qs + 64 * 65;
    float* Vs  = Ks + 64 * 65;
    float* Ps  = Vs + 64 * 65;
    float* red = Ps + 64 * 65;       // 4*64

    const int qb = (int)gridDim.x - 1 - (int)blockIdx.x; // big tiles first
    const int bh = blockIdx.y;       // 0..31
    const int b  = bh >> 4;
    const int h  = bh & 15;
    const int tid = threadIdx.x;
    const int i  = tid & 63;         // row within q tile
    const int jg = tid >> 6;         // 0..3
    const int j0 = jg * 16;

    const float* base = qkv + (size_t)b * SEQ * (3 * D_MODEL) + h * D_K;
    // row s: q at base + s*3072, k at +1024, v at +2048

    // Load Q tile (64 x 64)
    for (int u = tid; u < 64 * 16; u += 256) {
        int r  = u >> 4;
        int c4 = (u & 15) * 4;
        float4 v = *(const float4*)(base + (size_t)(qb * 64 + r) * 3072 + c4);
        Qs[r * 65 + c4 + 0] = v.x; Qs[r * 65 + c4 + 1] = v.y;
        Qs[r * 65 + c4 + 2] = v.z; Qs[r * 65 + c4 + 3] = v.w;
    }

    float m_i = -1e30f, l_i = 0.f;
    float O[16];
    #pragma unroll
    for (int c = 0; c < 16; c++) O[c] = 0.f;

    for (int kb = 0; kb <= qb; kb++) {
        __syncthreads(); // previous-iter readers of Ks/Vs/Ps done (also covers Q load)
        for (int u = tid; u < 64 * 16; u += 256) {
            int r  = u >> 4;
            int c4 = (u & 15) * 4;
            const float* krow = base + (size_t)(kb * 64 + r) * 3072 + D_MODEL + c4;
            float4 kv = *(const float4*)krow;
            Ks[r * 65 + c4 + 0] = kv.x; Ks[r * 65 + c4 + 1] = kv.y;
            Ks[r * 65 + c4 + 2] = kv.z; Ks[r * 65 + c4 + 3] = kv.w;
            const float* vrow = base + (size_t)(kb * 64 + r) * 3072 + 2 * D_MODEL + c4;
            float4 vv = *(const float4*)vrow;
            Vs[r * 65 + c4 + 0] = vv.x; Vs[r * 65 + c4 + 1] = vv.y;
            Vs[r * 65 + c4 + 2] = vv.z; Vs[r * 65 + c4 + 3] = vv.w;
        }
        __syncthreads();

        // S[i][j0..j0+15] = (Q K^T)[i][j] * SCALE, causal-masked on diag tile
        float s[16];
        #pragma unroll
        for (int jj = 0; jj < 16; jj++) s[jj] = 0.f;
        for (int k = 0; k < 64; k++) {
            float q = Qs[i * 65 + k];
            #pragma unroll
            for (int jj = 0; jj < 16; jj++)
                s[jj] += q * Ks[(j0 + jj) * 65 + k];
        }
        const bool diag = (kb == qb);
        float pmax = -1e30f;
        #pragma unroll
        for (int jj = 0; jj < 16; jj++) {
            float val = s[jj] * SCALE;
            if (diag && (j0 + jj) > i) val = -1e9f;
            s[jj] = val;
            pmax = fmaxf(pmax, val);
        }

        // Row max across the 4 col-groups
        red[jg * 64 + i] = pmax;
        __syncthreads();
        float rmax = fmaxf(fmaxf(red[i], red[64 + i]),
                           fmaxf(red[128 + i], red[192 + i]));
        float m_new = fmaxf(m_i, rmax);

        float psum = 0.f;
        #pragma unroll
        for (int jj = 0; jj < 16; jj++) {
            float p = __expf(s[jj] - m_new);
            Ps[i * 65 + j0 + jj] = p;
            psum += p;
        }
        __syncthreads(); // red(max) consumed, Ps visible after next barrier
        red[jg * 64 + i] = psum;
        __syncthreads();
        float rsum = red[i] + red[64 + i] + red[128 + i] + red[192 + i];

        float alpha = __expf(m_i - m_new);
        l_i = l_i * alpha + rsum;
        m_i = m_new;
        #pragma unroll
        for (int c = 0; c < 16; c++) O[c] *= alpha;

        // O[i][c0..c0+15] += P[i][:] @ V[:, c0..c0+15]
        for (int j = 0; j < 64; j++) {
            float p = Ps[i * 65 + j];
            #pragma unroll
            for (int c = 0; c < 16; c++)
                O[c] += p * Vs[j * 65 + j0 + c];
        }
    }

    float inv_l = 1.f / l_i;
    float* out = ctx + ((size_t)(b * SEQ + qb * 64 + i) * D_MODEL) + h * D_K + j0;
    #pragma unroll
    for (int c = 0; c < 16; c++) out[c] = O[c] * inv_l;
}

// ---------------------------------------------------------------------------
extern "C" void kernel_launch(void* const* d_in, const int* in_sizes, int n_in,
                              void* d_out, int out_size)
{
    const float* query = (const float*)d_in[0];
    // d_in[1]=key, d_in[2]=value (ignored by the reference), d_in[3]=mask (causal, hardcoded)
    const float* w_qkv = (const float*)d_in[4];
    const float* w_o   = (const float*)d_in[5];
    float* out = (float*)d_out;

    float* qkv = nullptr;
    float* ctx = nullptr;
    cudaGetSymbolAddress((void**)&qkv, g_qkv);
    cudaGetSymbolAddress((void**)&ctx, g_ctx);

    const int M = BATCH * SEQ;            // 4096
    const size_t smem = ATTN_SMEM_FLOATS * sizeof(float); // ~67.6 KB
    cudaFuncSetAttribute(attn_kernel,
                         cudaFuncAttributeMaxDynamicSharedMemorySize, (int)smem);

    // 1) qkv = query @ w_qkv   [4096,1024]x[1024,3072]
    dim3 g1(3 * D_MODEL / 128, M / 128);
    gemm_kernel<<<g1, 256>>>(query, w_qkv, qkv, M, 3 * D_MODEL, D_MODEL);

    // 2) causal flash attention -> ctx [B,S,D]
    dim3 ga(SEQ / 64, BATCH * N_HEADS);
    attn_kernel<<<ga, 256, smem>>>(qkv, ctx);

    // 3) out = ctx @ w_o       [4096,1024]x[1024,1024]
    dim3 g2(D_MODEL / 128, M / 128);
    gemm_kernel<<<g2, 256>>>(ctx, w_o, out, M, D_MODEL, D_MODEL);
}

// round 3
// speedup vs baseline: 1.5430x; 1.5430x over previous
#include <cuda_runtime.h>
#include <cuda_bf16.h>
#include <math.h>
#include <cstdint>

#define D_MODEL 1024
#define N_HEADS 16
#define D_K     64
#define BATCH   2
#define SEQ     2048
#define SCALE   0.125f  /* 1/sqrt(64) */
#define M_ROWS  (BATCH * SEQ)   /* 4096 */

// ---------------------------------------------------------------------------
// Scratch (allocation-free rule: __device__ globals)
// ---------------------------------------------------------------------------
__device__ float g_qkv[(size_t)BATCH * SEQ * 3 * D_MODEL];   // [B,S,3D]
__device__ float g_ctx[(size_t)BATCH * SEQ * D_MODEL];       // [B,S,D]
__device__ __nv_bfloat16 g_Ahi[(size_t)M_ROWS * D_MODEL];
__device__ __nv_bfloat16 g_Alo[(size_t)M_ROWS * D_MODEL];
__device__ __nv_bfloat16 g_W1hi[(size_t)3 * D_MODEL * D_MODEL]; // w_qkv^T [3072,1024]
__device__ __nv_bfloat16 g_W1lo[(size_t)3 * D_MODEL * D_MODEL];
__device__ __nv_bfloat16 g_W2hi[(size_t)D_MODEL * D_MODEL];     // w_o^T [1024,1024]
__device__ __nv_bfloat16 g_W2lo[(size_t)D_MODEL * D_MODEL];

// ---------------------------------------------------------------------------
// Helpers
// ---------------------------------------------------------------------------
__device__ __forceinline__ uint32_t smem_u32(const void* p) {
    uint32_t a;
    asm("{ .reg .u64 t; cvta.to.shared.u64 t, %1; cvt.u32.u64 %0, t; }"
        : "=r"(a) : "l"(p));
    return a;
}

#define CP_ASYNC16(saddr, gptr) \
    asm volatile("cp.async.cg.shared.global [%0], [%1], 16;" :: "r"(saddr), "l"(gptr))
#define CP_COMMIT() asm volatile("cp.async.commit_group;")
#define CP_WAIT1()  asm volatile("cp.async.wait_group 1;")
#define CP_WAIT0()  asm volatile("cp.async.wait_group 0;")

#define LDSM4(r, addr) \
    asm volatile("ldmatrix.sync.aligned.m8n8.x4.shared.b16 {%0,%1,%2,%3}, [%4];" \
        : "=r"((r)[0]), "=r"((r)[1]), "=r"((r)[2]), "=r"((r)[3]) : "r"(addr))

#define MMA16816(d, a, b0, b1) \
    asm volatile("mma.sync.aligned.m16n8k16.row.col.f32.bf16.bf16.f32 " \
        "{%0,%1,%2,%3}, {%4,%5,%6,%7}, {%8,%9}, {%0,%1,%2,%3};" \
        : "+f"((d)[0]), "+f"((d)[1]), "+f"((d)[2]), "+f"((d)[3]) \
        : "r"((a)[0]), "r"((a)[1]), "r"((a)[2]), "r"((a)[3]), "r"(b0), "r"(b1))

// ---------------------------------------------------------------------------
// Prep kernels
// ---------------------------------------------------------------------------
__global__ void split_f32_kernel(const float* __restrict__ x,
                                 __nv_bfloat16* __restrict__ hi,
                                 __nv_bfloat16* __restrict__ lo, int n4) {
    int i = blockIdx.x * blockDim.x + threadIdx.x;
    if (i >= n4) return;
    float4 v = ((const float4*)x)[i];
    __nv_bfloat16 h0 = __float2bfloat16(v.x), h1 = __float2bfloat16(v.y);
    __nv_bfloat16 h2 = __float2bfloat16(v.z), h3 = __float2bfloat16(v.w);
    __nv_bfloat16 l0 = __float2bfloat16(v.x - __bfloat162float(h0));
    __nv_bfloat16 l1 = __float2bfloat16(v.y - __bfloat162float(h1));
    __nv_bfloat16 l2 = __float2bfloat16(v.z - __bfloat162float(h2));
    __nv_bfloat16 l3 = __float2bfloat16(v.w - __bfloat162float(h3));
    __nv_bfloat162* hp = (__nv_bfloat162*)(hi + (size_t)i * 4);
    __nv_bfloat162* lp = (__nv_bfloat162*)(lo + (size_t)i * 4);
    hp[0] = __nv_bfloat162(h0, h1); hp[1] = __nv_bfloat162(h2, h3);
    lp[0] = __nv_bfloat162(l0, l1); lp[1] = __nv_bfloat162(l2, l3);
}

// W [K,N] fp32 row-major -> T_hi/T_lo [N,K] bf16 row-major
__global__ void transpose_split_kernel(const float* __restrict__ W,
                                       __nv_bfloat16* __restrict__ Thi,
                                       __nv_bfloat16* __restrict__ Tlo,
                                       int K, int N) {
    __shared__ float t[32][33];
    int n0 = blockIdx.x * 32, k0 = blockIdx.y * 32;
    int tx = threadIdx.x, ty = threadIdx.y;
    #pragma unroll
    for (int i = ty; i < 32; i += 8)
        t[i][tx] = W[(size_t)(k0 + i) * N + n0 + tx];
    __syncthreads();
    #pragma unroll
    for (int i = ty; i < 32; i += 8) {
        float v = t[tx][i];
        __nv_bfloat16 h = __float2bfloat16(v);
        size_t o = (size_t)(n0 + i) * K + k0 + tx;
        Thi[o] = h;
        Tlo[o] = __float2bfloat16(v - __bfloat162float(h));
    }
}

// ---------------------------------------------------------------------------
// HMMA bf16x3 GEMM: C[M,N](fp32) = A[M,K] @ Wt[N,K]^T
// CTA 128x128, BK=64, 8 warps (2x4), double-buffered cp.async, swizzled smem.
// smem per stage: Ahi,Alo,Bhi,Blo tiles, each 128 rows x 128 bytes.
// ---------------------------------------------------------------------------
#define TILE_BYTES  (128 * 128)
#define STAGE_BYTES (4 * TILE_BYTES)  /* 65536 */
#define SM_A_HI 0
#define SM_A_LO TILE_BYTES
#define SM_B_HI (2 * TILE_BYTES)
#define SM_B_LO (3 * TILE_BYTES)
#define GEMM_SMEM (2 * STAGE_BYTES)   /* 131072 */

__global__ void __launch_bounds__(256) gemm_hmma_kernel(
    const __nv_bfloat16* __restrict__ Ahi, const __nv_bfloat16* __restrict__ Alo,
    const __nv_bfloat16* __restrict__ Bhi, const __nv_bfloat16* __restrict__ Blo,
    float* __restrict__ C, int M, int N, int K)
{
    extern __shared__ char smem[];
    const uint32_t sbase = smem_u32(smem);
    const int tid = threadIdx.x;
    const int lid = tid & 31;
    const int wid = tid >> 5;
    const int wm  = wid >> 2;   // 0..1
    const int wn  = wid & 3;    // 0..3
    const int m0 = blockIdx.y * 128;
    const int n0 = blockIdx.x * 128;

    // cp.async assignment: thread -> (row = tid/8 + 32u, chunk = tid%8)
    const int cr = tid >> 3;
    const int cc = tid & 7;
    const uint32_t csw = (uint32_t)((cc ^ (cr & 7)) << 4);  // (cr+32u)&7 == cr&7

    const int niter = K / 64;

    // --- prefetch stage 0
    {
        const int kofs = 0;
        uint32_t sb = sbase;
        #pragma unroll
        for (int u = 0; u < 4; u++) {
            int r = cr + u * 32;
            uint32_t so = (uint32_t)(r * 128) + csw;
            size_t ga = (size_t)(m0 + r) * K + kofs + cc * 8;
            size_t gb = (size_t)(n0 + r) * K + kofs + cc * 8;
            CP_ASYNC16(sb + SM_A_HI + so, Ahi + ga);
            CP_ASYNC16(sb + SM_A_LO + so, Alo + ga);
            CP_ASYNC16(sb + SM_B_HI + so, Bhi + gb);
            CP_ASYNC16(sb + SM_B_LO + so, Blo + gb);
        }
        CP_COMMIT();
    }

    float acc[4][4][4];
    #pragma unroll
    for (int i = 0; i < 4; i++)
        #pragma unroll
        for (int j = 0; j < 4; j++)
            #pragma unroll
            for (int k = 0; k < 4; k++) acc[i][j][k] = 0.f;

    // ldmatrix per-lane static pieces
    const int a_rowlane = lid & 15;          // row within 16-row tile
    const int a_csel    = lid >> 4;          // 0/1 -> k chunk select
    const int b_rowlane = ((lid >> 4) << 3) + (lid & 7);  // row within 16-row n-tile
    const int b_csel    = (lid >> 3) & 1;
    const int sw_lane   = lid & 7;

    for (int kt = 0; kt < niter; kt++) {
        if (kt + 1 < niter) {
            const int kofs = (kt + 1) * 64;
            uint32_t sb = sbase + ((kt + 1) & 1) * STAGE_BYTES;
            #pragma unroll
            for (int u = 0; u < 4; u++) {
                int r = cr + u * 32;
                uint32_t so = (uint32_t)(r * 128) + csw;
                size_t ga = (size_t)(m0 + r) * K + kofs + cc * 8;
                size_t gb = (size_t)(n0 + r) * K + kofs + cc * 8;
                CP_ASYNC16(sb + SM_A_HI + so, Ahi + ga);
                CP_ASYNC16(sb + SM_A_LO + so, Alo + ga);
                CP_ASYNC16(sb + SM_B_HI + so, Bhi + gb);
                CP_ASYNC16(sb + SM_B_LO + so, Blo + gb);
            }
            CP_COMMIT();
            CP_WAIT1();
        } else {
            CP_WAIT0();
        }
        __syncthreads();

        const uint32_t sb = sbase + (kt & 1) * STAGE_BYTES;
        const uint32_t abase0 = sb + SM_A_HI + (uint32_t)((wm * 64 + a_rowlane) * 128);
        const uint32_t bbase0 = sb + SM_B_HI + (uint32_t)((wn * 32 + b_rowlane) * 128);

        #pragma unroll
        for (int ks = 0; ks < 4; ks++) {
            const uint32_t axor = (uint32_t)(((ks * 2 + a_csel) ^ sw_lane) << 4);
            const uint32_t bxor = (uint32_t)(((ks * 2 + b_csel) ^ sw_lane) << 4);
            const uint32_t abase = abase0 + axor;
            const uint32_t bbase = bbase0 + bxor;

            uint32_t ah[4][4], bh[2][4], bl[2][4];
            #pragma unroll
            for (int tm = 0; tm < 4; tm++) LDSM4(ah[tm], abase + tm * 2048);
            #pragma unroll
            for (int tg = 0; tg < 2; tg++) LDSM4(bh[tg], bbase + tg * 2048);
            #pragma unroll
            for (int tg = 0; tg < 2; tg++) LDSM4(bl[tg], bbase + TILE_BYTES + tg * 2048);

            // Ah*Bh + Ah*Bl
            #pragma unroll
            for (int tm = 0; tm < 4; tm++) {
                #pragma unroll
                for (int tg = 0; tg < 2; tg++) {
                    MMA16816(acc[tm][tg * 2 + 0], ah[tm], bh[tg][0], bh[tg][1]);
                    MMA16816(acc[tm][tg * 2 + 1], ah[tm], bh[tg][2], bh[tg][3]);
                    MMA16816(acc[tm][tg * 2 + 0], ah[tm], bl[tg][0], bl[tg][1]);
                    MMA16816(acc[tm][tg * 2 + 1], ah[tm], bl[tg][2], bl[tg][3]);
                }
            }
            // Al*Bh (reuse ah regs)
            #pragma unroll
            for (int tm = 0; tm < 4; tm++) LDSM4(ah[tm], abase + TILE_BYTES + tm * 2048);
            #pragma unroll
            for (int tm = 0; tm < 4; tm++) {
                #pragma unroll
                for (int tg = 0; tg < 2; tg++) {
                    MMA16816(acc[tm][tg * 2 + 0], ah[tm], bh[tg][0], bh[tg][1]);
                    MMA16816(acc[tm][tg * 2 + 1], ah[tm], bh[tg][2], bh[tg][3]);
                }
            }
        }
        __syncthreads();
    }

    // Epilogue: direct fp32 stores
    const int erow = (lid >> 2);
    const int ecol = (lid & 3) * 2;
    #pragma unroll
    for (int tm = 0; tm < 4; tm++) {
        #pragma unroll
        for (int tg = 0; tg < 4; tg++) {
            int row = m0 + wm * 64 + tm * 16 + erow;
            int col = n0 + wn * 32 + tg * 8 + ecol;
            *(float2*)(C + (size_t)row * N + col) =
                make_float2(acc[tm][tg][0], acc[tm][tg][1]);
            *(float2*)(C + (size_t)(row + 8) * N + col) =
                make_float2(acc[tm][tg][2], acc[tm][tg][3]);
        }
    }
}

// ---------------------------------------------------------------------------
// Flash attention (causal), fp32 SIMT (unchanged)
// ---------------------------------------------------------------------------
#define ATTN_SMEM_FLOATS (4 * 64 * 65 + 256)

__global__ void __launch_bounds__(256) attn_kernel(
    const float* __restrict__ qkv, float* __restrict__ ctx)
{
    extern __shared__ float sm[];
    float* Qs  = sm;
    float* Ks  = Qs + 64 * 65;
    float* Vs  = Ks + 64 * 65;
    float* Ps  = Vs + 64 * 65;
    float* red = Ps + 64 * 65;

    const int qb = (int)gridDim.x - 1 - (int)blockIdx.x;
    const int bh = blockIdx.y;
    const int b  = bh >> 4;
    const int h  = bh & 15;
    const int tid = threadIdx.x;
    const int i  = tid & 63;
    const int jg = tid >> 6;
    const int j0 = jg * 16;

    const float* base = qkv + (size_t)b * SEQ * (3 * D_MODEL) + h * D_K;

    for (int u = tid; u < 64 * 16; u += 256) {
        int r  = u >> 4;
        int c4 = (u & 15) * 4;
        float4 v = *(const float4*)(base + (size_t)(qb * 64 + r) * 3072 + c4);
        Qs[r * 65 + c4 + 0] = v.x; Qs[r * 65 + c4 + 1] = v.y;
        Qs[r * 65 + c4 + 2] = v.z; Qs[r * 65 + c4 + 3] = v.w;
    }

    float m_i = -1e30f, l_i = 0.f;
    float O[16];
    #pragma unroll
    for (int c = 0; c < 16; c++) O[c] = 0.f;

    for (int kb = 0; kb <= qb; kb++) {
        __syncthreads();
        for (int u = tid; u < 64 * 16; u += 256) {
            int r  = u >> 4;
            int c4 = (u & 15) * 4;
            const float* krow = base + (size_t)(kb * 64 + r) * 3072 + D_MODEL + c4;
            float4 kv = *(const float4*)krow;
            Ks[r * 65 + c4 + 0] = kv.x; Ks[r * 65 + c4 + 1] = kv.y;
            Ks[r * 65 + c4 + 2] = kv.z; Ks[r * 65 + c4 + 3] = kv.w;
            const float* vrow = base + (size_t)(kb * 64 + r) * 3072 + 2 * D_MODEL + c4;
            float4 vv = *(const float4*)vrow;
            Vs[r * 65 + c4 + 0] = vv.x; Vs[r * 65 + c4 + 1] = vv.y;
            Vs[r * 65 + c4 + 2] = vv.z; Vs[r * 65 + c4 + 3] = vv.w;
        }
        __syncthreads();

        float s[16];
        #pragma unroll
        for (int jj = 0; jj < 16; jj++) s[jj] = 0.f;
        for (int k = 0; k < 64; k++) {
            float q = Qs[i * 65 + k];
            #pragma unroll
            for (int jj = 0; jj < 16; jj++)
                s[jj] += q * Ks[(j0 + jj) * 65 + k];
        }
        const bool diag = (kb == qb);
        float pmax = -1e30f;
        #pragma unroll
        for (int jj = 0; jj < 16; jj++) {
            float val = s[jj] * SCALE;
            if (diag && (j0 + jj) > i) val = -1e9f;
            s[jj] = val;
            pmax = fmaxf(pmax, val);
        }

        red[jg * 64 + i] = pmax;
        __syncthreads();
        float rmax = fmaxf(fmaxf(red[i], red[64 + i]),
                           fmaxf(red[128 + i], red[192 + i]));
        float m_new = fmaxf(m_i, rmax);

        float psum = 0.f;
        #pragma unroll
        for (int jj = 0; jj < 16; jj++) {
            float p = __expf(s[jj] - m_new);
            Ps[i * 65 + j0 + jj] = p;
            psum += p;
        }
        __syncthreads();
        red[jg * 64 + i] = psum;
        __syncthreads();
        float rsum = red[i] + red[64 + i] + red[128 + i] + red[192 + i];

        float alpha = __expf(m_i - m_new);
        l_i = l_i * alpha + rsum;
        m_i = m_new;
        #pragma unroll
        for (int c = 0; c < 16; c++) O[c] *= alpha;

        for (int j = 0; j < 64; j++) {
            float p = Ps[i * 65 + j];
            #pragma unroll
            for (int c = 0; c < 16; c++)
                O[c] += p * Vs[j * 65 + j0 + c];
        }
    }

    float inv_l = 1.f / l_i;
    float* out = ctx + ((size_t)(b * SEQ + qb * 64 + i) * D_MODEL) + h * D_K + j0;
    #pragma unroll
    for (int c = 0; c < 16; c++) out[c] = O[c] * inv_l;
}

// ---------------------------------------------------------------------------
extern "C" void kernel_launch(void* const* d_in, const int* in_sizes, int n_in,
                              void* d_out, int out_size)
{
    const float* query = (const float*)d_in[0];
    const float* w_qkv = (const float*)d_in[4];
    const float* w_o   = (const float*)d_in[5];
    float* out = (float*)d_out;

    float *qkv, *ctx;
    __nv_bfloat16 *Ahi, *Alo, *W1hi, *W1lo, *W2hi, *W2lo;
    cudaGetSymbolAddress((void**)&qkv,  g_qkv);
    cudaGetSymbolAddress((void**)&ctx,  g_ctx);
    cudaGetSymbolAddress((void**)&Ahi,  g_Ahi);
    cudaGetSymbolAddress((void**)&Alo,  g_Alo);
    cudaGetSymbolAddress((void**)&W1hi, g_W1hi);
    cudaGetSymbolAddress((void**)&W1lo, g_W1lo);
    cudaGetSymbolAddress((void**)&W2hi, g_W2hi);
    cudaGetSymbolAddress((void**)&W2lo, g_W2lo);

    cudaFuncSetAttribute(gemm_hmma_kernel,
                         cudaFuncAttributeMaxDynamicSharedMemorySize, GEMM_SMEM);
    const size_t attn_smem = ATTN_SMEM_FLOATS * sizeof(float);
    cudaFuncSetAttribute(attn_kernel,
                         cudaFuncAttributeMaxDynamicSharedMemorySize, (int)attn_smem);

    // Prep: weight transposes + query split
    {
        dim3 b(32, 8);
        transpose_split_kernel<<<dim3(3 * D_MODEL / 32, D_MODEL / 32), b>>>(
            w_qkv, W1hi, W1lo, D_MODEL, 3 * D_MODEL);
        transpose_split_kernel<<<dim3(D_MODEL / 32, D_MODEL / 32), b>>>(
            w_o, W2hi, W2lo, D_MODEL, D_MODEL);
        int n4 = M_ROWS * D_MODEL / 4;
        split_f32_kernel<<<(n4 + 255) / 256, 256>>>(query, Ahi, Alo, n4);
    }

    // 1) qkv = query @ w_qkv  [4096,3072]
    gemm_hmma_kernel<<<dim3(3 * D_MODEL / 128, M_ROWS / 128), 256, GEMM_SMEM>>>(
        Ahi, Alo, W1hi, W1lo, qkv, M_ROWS, 3 * D_MODEL, D_MODEL);

    // 2) causal flash attention -> ctx
    attn_kernel<<<dim3(SEQ / 64, BATCH * N_HEADS), 256, attn_smem>>>(qkv, ctx);

    // 3) out = ctx @ w_o  [4096,1024]
    {
        int n4 = M_ROWS * D_MODEL / 4;
        split_f32_kernel<<<(n4 + 255) / 256, 256>>>(ctx, Ahi, Alo, n4);
    }
    gemm_hmma_kernel<<<dim3(D_MODEL / 128, M_ROWS / 128), 256, GEMM_SMEM>>>(
        Ahi, Alo, W2hi, W2lo, out, M_ROWS, D_MODEL, D_MODEL);
}

// round 4
// speedup vs baseline: 3.5585x; 2.3063x over previous
#include <cuda_runtime.h>
#include <cuda_bf16.h>
#include <math.h>
#include <cstdint>

#define D_MODEL 1024
#define N_HEADS 16
#define D_K     64
#define BATCH   2
#define SEQ     2048
#define SCALE   0.125f  /* 1/sqrt(64) */
#define M_ROWS  (BATCH * SEQ)   /* 4096 */

// ---------------------------------------------------------------------------
// Scratch (allocation-free rule: __device__ globals)
// ---------------------------------------------------------------------------
__device__ __nv_bfloat16 g_Ahi[(size_t)M_ROWS * D_MODEL];       // activation split / ctx split
__device__ __nv_bfloat16 g_Alo[(size_t)M_ROWS * D_MODEL];
__device__ __nv_bfloat16 g_QKVhi[(size_t)M_ROWS * 3 * D_MODEL]; // qkv split [4096,3072]
__device__ __nv_bfloat16 g_QKVlo[(size_t)M_ROWS * 3 * D_MODEL];
__device__ __nv_bfloat16 g_W1hi[(size_t)3 * D_MODEL * D_MODEL]; // w_qkv^T [3072,1024]
__device__ __nv_bfloat16 g_W1lo[(size_t)3 * D_MODEL * D_MODEL];
__device__ __nv_bfloat16 g_W2hi[(size_t)D_MODEL * D_MODEL];     // w_o^T [1024,1024]
__device__ __nv_bfloat16 g_W2lo[(size_t)D_MODEL * D_MODEL];

// ---------------------------------------------------------------------------
// Helpers
// ---------------------------------------------------------------------------
__device__ __forceinline__ uint32_t smem_u32(const void* p) {
    uint32_t a;
    asm("{ .reg .u64 t; cvta.to.shared.u64 t, %1; cvt.u32.u64 %0, t; }"
        : "=r"(a) : "l"(p));
    return a;
}

#define CP_ASYNC16(saddr, gptr) \
    asm volatile("cp.async.cg.shared.global [%0], [%1], 16;" :: "r"(saddr), "l"(gptr))
#define CP_COMMIT() asm volatile("cp.async.commit_group;")
#define CP_WAIT1()  asm volatile("cp.async.wait_group 1;")
#define CP_WAIT0()  asm volatile("cp.async.wait_group 0;")

#define LDSM4(r, addr) \
    asm volatile("ldmatrix.sync.aligned.m8n8.x4.shared.b16 {%0,%1,%2,%3}, [%4];" \
        : "=r"((r)[0]), "=r"((r)[1]), "=r"((r)[2]), "=r"((r)[3]) : "r"(addr))
#define LDSM4T(r, addr) \
    asm volatile("ldmatrix.sync.aligned.m8n8.x4.trans.shared.b16 {%0,%1,%2,%3}, [%4];" \
        : "=r"((r)[0]), "=r"((r)[1]), "=r"((r)[2]), "=r"((r)[3]) : "r"(addr))

#define MMA16816(d, a, b0, b1) \
    asm volatile("mma.sync.aligned.m16n8k16.row.col.f32.bf16.bf16.f32 " \
        "{%0,%1,%2,%3}, {%4,%5,%6,%7}, {%8,%9}, {%0,%1,%2,%3};" \
        : "+f"((d)[0]), "+f"((d)[1]), "+f"((d)[2]), "+f"((d)[3]) \
        : "r"((a)[0]), "r"((a)[1]), "r"((a)[2]), "r"((a)[3]), "r"(b0), "r"(b1))

// split two fp32 into bf16 hi pair + bf16 lo pair (packed as u32)
__device__ __forceinline__ void split2(float x, float y, uint32_t& h, uint32_t& l) {
    __nv_bfloat162 bh = __floats2bfloat162_rn(x, y);
    float2 hf = __bfloat1622float2(bh);
    __nv_bfloat162 bl = __floats2bfloat162_rn(x - hf.x, y - hf.y);
    h = *(uint32_t*)&bh;
    l = *(uint32_t*)&bl;
}

// ---------------------------------------------------------------------------
// Prep kernels
// ---------------------------------------------------------------------------
__global__ void split_f32_kernel(const float* __restrict__ x,
                                 __nv_bfloat16* __restrict__ hi,
                                 __nv_bfloat16* __restrict__ lo, int n4) {
    int i = blockIdx.x * blockDim.x + threadIdx.x;
    if (i >= n4) return;
    float4 v = ((const float4*)x)[i];
    uint32_t h0, l0, h1, l1;
    split2(v.x, v.y, h0, l0);
    split2(v.z, v.w, h1, l1);
    uint2* hp = (uint2*)(hi + (size_t)i * 4);
    uint2* lp = (uint2*)(lo + (size_t)i * 4);
    *hp = make_uint2(h0, h1);
    *lp = make_uint2(l0, l1);
}

// W [K,N] fp32 row-major -> T_hi/T_lo [N,K] bf16 row-major
__global__ void transpose_split_kernel(const float* __restrict__ W,
                                       __nv_bfloat16* __restrict__ Thi,
                                       __nv_bfloat16* __restrict__ Tlo,
                                       int K, int N) {
    __shared__ float t[32][33];
    int n0 = blockIdx.x * 32, k0 = blockIdx.y * 32;
    int tx = threadIdx.x, ty = threadIdx.y;
    #pragma unroll
    for (int i = ty; i < 32; i += 8)
        t[i][tx] = W[(size_t)(k0 + i) * N + n0 + tx];
    __syncthreads();
    #pragma unroll
    for (int i = ty; i < 32; i += 8) {
        float v = t[tx][i];
        __nv_bfloat16 h = __float2bfloat16(v);
        size_t o = (size_t)(n0 + i) * K + k0 + tx;
        Thi[o] = h;
        Tlo[o] = __float2bfloat16(v - __bfloat162float(h));
    }
}

// ---------------------------------------------------------------------------
// HMMA bf16x3 GEMM: C = A[M,K] @ Wt[N,K]^T
// SPLIT_OUT=false: write fp32 C.  SPLIT_OUT=true: write bf16 hi/lo split.
// ---------------------------------------------------------------------------
#define TILE_BYTES  (128 * 128)
#define STAGE_BYTES (4 * TILE_BYTES)
#define SM_A_HI 0
#define SM_A_LO TILE_BYTES
#define SM_B_HI (2 * TILE_BYTES)
#define SM_B_LO (3 * TILE_BYTES)
#define GEMM_SMEM (2 * STAGE_BYTES)

template <bool SPLIT_OUT>
__global__ void __launch_bounds__(256) gemm_hmma_kernel(
    const __nv_bfloat16* __restrict__ Ahi, const __nv_bfloat16* __restrict__ Alo,
    const __nv_bfloat16* __restrict__ Bhi, const __nv_bfloat16* __restrict__ Blo,
    float* __restrict__ C,
    __nv_bfloat16* __restrict__ Chi, __nv_bfloat16* __restrict__ Clo,
    int M, int N, int K)
{
    extern __shared__ char smem[];
    const uint32_t sbase = smem_u32(smem);
    const int tid = threadIdx.x;
    const int lid = tid & 31;
    const int wid = tid >> 5;
    const int wm  = wid >> 2;
    const int wn  = wid & 3;
    const int m0 = blockIdx.y * 128;
    const int n0 = blockIdx.x * 128;

    const int cr = tid >> 3;
    const int cc = tid & 7;
    const uint32_t csw = (uint32_t)((cc ^ (cr & 7)) << 4);

    const int niter = K / 64;

    {
        uint32_t sb = sbase;
        #pragma unroll
        for (int u = 0; u < 4; u++) {
            int r = cr + u * 32;
            uint32_t so = (uint32_t)(r * 128) + csw;
            size_t ga = (size_t)(m0 + r) * K + cc * 8;
            size_t gb = (size_t)(n0 + r) * K + cc * 8;
            CP_ASYNC16(sb + SM_A_HI + so, Ahi + ga);
            CP_ASYNC16(sb + SM_A_LO + so, Alo + ga);
            CP_ASYNC16(sb + SM_B_HI + so, Bhi + gb);
            CP_ASYNC16(sb + SM_B_LO + so, Blo + gb);
        }
        CP_COMMIT();
    }

    float acc[4][4][4];
    #pragma unroll
    for (int i = 0; i < 4; i++)
        #pragma unroll
        for (int j = 0; j < 4; j++)
            #pragma unroll
            for (int k = 0; k < 4; k++) acc[i][j][k] = 0.f;

    const int a_rowlane = lid & 15;
    const int a_csel    = lid >> 4;
    const int b_rowlane = ((lid >> 4) << 3) + (lid & 7);
    const int b_csel    = (lid >> 3) & 1;
    const int sw_lane   = lid & 7;

    for (int kt = 0; kt < niter; kt++) {
        if (kt + 1 < niter) {
            const int kofs = (kt + 1) * 64;
            uint32_t sb = sbase + ((kt + 1) & 1) * STAGE_BYTES;
            #pragma unroll
            for (int u = 0; u < 4; u++) {
                int r = cr + u * 32;
                uint32_t so = (uint32_t)(r * 128) + csw;
                size_t ga = (size_t)(m0 + r) * K + kofs + cc * 8;
                size_t gb = (size_t)(n0 + r) * K + kofs + cc * 8;
                CP_ASYNC16(sb + SM_A_HI + so, Ahi + ga);
                CP_ASYNC16(sb + SM_A_LO + so, Alo + ga);
                CP_ASYNC16(sb + SM_B_HI + so, Bhi + gb);
                CP_ASYNC16(sb + SM_B_LO + so, Blo + gb);
            }
            CP_COMMIT();
            CP_WAIT1();
        } else {
            CP_WAIT0();
        }
        __syncthreads();

        const uint32_t sb = sbase + (kt & 1) * STAGE_BYTES;
        const uint32_t abase0 = sb + SM_A_HI + (uint32_t)((wm * 64 + a_rowlane) * 128);
        const uint32_t bbase0 = sb + SM_B_HI + (uint32_t)((wn * 32 + b_rowlane) * 128);

        #pragma unroll
        for (int ks = 0; ks < 4; ks++) {
            const uint32_t axor = (uint32_t)(((ks * 2 + a_csel) ^ sw_lane) << 4);
            const uint32_t bxor = (uint32_t)(((ks * 2 + b_csel) ^ sw_lane) << 4);
            const uint32_t abase = abase0 + axor;
            const uint32_t bbase = bbase0 + bxor;

            uint32_t ah[4][4], bh[2][4], bl[2][4];
            #pragma unroll
            for (int tm = 0; tm < 4; tm++) LDSM4(ah[tm], abase + tm * 2048);
            #pragma unroll
            for (int tg = 0; tg < 2; tg++) LDSM4(bh[tg], bbase + tg * 2048);
            #pragma unroll
            for (int tg = 0; tg < 2; tg++) LDSM4(bl[tg], bbase + TILE_BYTES + tg * 2048);

            #pragma unroll
            for (int tm = 0; tm < 4; tm++) {
                #pragma unroll
                for (int tg = 0; tg < 2; tg++) {
                    MMA16816(acc[tm][tg * 2 + 0], ah[tm], bh[tg][0], bh[tg][1]);
                    MMA16816(acc[tm][tg * 2 + 1], ah[tm], bh[tg][2], bh[tg][3]);
                    MMA16816(acc[tm][tg * 2 + 0], ah[tm], bl[tg][0], bl[tg][1]);
                    MMA16816(acc[tm][tg * 2 + 1], ah[tm], bl[tg][2], bl[tg][3]);
                }
            }
            #pragma unroll
            for (int tm = 0; tm < 4; tm++) LDSM4(ah[tm], abase + TILE_BYTES + tm * 2048);
            #pragma unroll
            for (int tm = 0; tm < 4; tm++) {
                #pragma unroll
                for (int tg = 0; tg < 2; tg++) {
                    MMA16816(acc[tm][tg * 2 + 0], ah[tm], bh[tg][0], bh[tg][1]);
                    MMA16816(acc[tm][tg * 2 + 1], ah[tm], bh[tg][2], bh[tg][3]);
                }
            }
        }
        __syncthreads();
    }

    const int erow = (lid >> 2);
    const int ecol = (lid & 3) * 2;
    #pragma unroll
    for (int tm = 0; tm < 4; tm++) {
        #pragma unroll
        for (int tg = 0; tg < 4; tg++) {
            int row = m0 + wm * 64 + tm * 16 + erow;
            int col = n0 + wn * 32 + tg * 8 + ecol;
            if (SPLIT_OUT) {
                uint32_t h, l;
                split2(acc[tm][tg][0], acc[tm][tg][1], h, l);
                *(uint32_t*)(Chi + (size_t)row * N + col) = h;
                *(uint32_t*)(Clo + (size_t)row * N + col) = l;
                split2(acc[tm][tg][2], acc[tm][tg][3], h, l);
                *(uint32_t*)(Chi + (size_t)(row + 8) * N + col) = h;
                *(uint32_t*)(Clo + (size_t)(row + 8) * N + col) = l;
            } else {
                *(float2*)(C + (size_t)row * N + col) =
                    make_float2(acc[tm][tg][0], acc[tm][tg][1]);
                *(float2*)(C + (size_t)(row + 8) * N + col) =
                    make_float2(acc[tm][tg][2], acc[tm][tg][3]);
            }
        }
    }
}

// ---------------------------------------------------------------------------
// HMMA flash attention (causal), bf16x3 split.
// CTA: 128 q-rows x one (b,h). 8 warps, m16 per warp. K-tile = 64 keys,
// double-buffered cp.async. Smem rows padded to 144B (conflict-free ldmatrix).
// ---------------------------------------------------------------------------
#define AQ_HI 0
#define AQ_LO (128 * 144)
#define AKV0  (2 * 128 * 144)          /* 36864 */
#define KV_STAGE (4 * 64 * 144)        /* 36864 */
#define A_KH 0
#define A_KL (64 * 144)
#define A_VH (2 * 64 * 144)
#define A_VL (3 * 64 * 144)
#define ATTN_SMEM (AKV0 + 2 * KV_STAGE) /* 110592 */

__device__ __forceinline__ void attn_load_kv(
    const __nv_bfloat16* __restrict__ qh, const __nv_bfloat16* __restrict__ ql,
    uint32_t dst, int grow0, int kcol, int tid)
{
    #pragma unroll
    for (int u = 0; u < 8; u++) {
        int piece = u >> 1;                       // 0:KH 1:KL 2:VH 3:VL
        int r = (u & 1) * 32 + (tid >> 3);
        int c = tid & 7;
        const __nv_bfloat16* src = (piece & 1) ? ql : qh;
        int col = kcol + ((piece >> 1) ? D_MODEL : 0) + c * 8;
        const __nv_bfloat16* g = src + (size_t)(grow0 + r) * 3072 + col;
        CP_ASYNC16(dst + piece * (64 * 144) + r * 144 + c * 16, g);
    }
}

__global__ void __launch_bounds__(256, 2) attn_hmma_kernel(
    const __nv_bfloat16* __restrict__ qkvh, const __nv_bfloat16* __restrict__ qkvl,
    __nv_bfloat16* __restrict__ outh, __nv_bfloat16* __restrict__ outl)
{
    extern __shared__ char smem[];
    const uint32_t sbase = smem_u32(smem);
    const int tid = threadIdx.x;
    const int lid = tid & 31;
    const int wm  = tid >> 5;

    const int qb = (int)gridDim.x - 1 - (int)blockIdx.x;  // big tiles first
    const int bh = blockIdx.y;
    const int b  = bh >> 4;
    const int h  = bh & 15;
    const int q0 = qb * 128;
    const int nkt = qb * 2 + 2;

    const int qcol = h * D_K;
    const int browQ = b * SEQ + q0;

    // --- issue Q loads (group 0)
    #pragma unroll
    for (int u = 0; u < 8; u++) {
        int arr = u >> 2;
        int r = (u & 3) * 32 + (tid >> 3);
        int c = tid & 7;
        const __nv_bfloat16* src = arr ? qkvl : qkvh;
        const __nv_bfloat16* g = src + (size_t)(browQ + r) * 3072 + qcol + c * 8;
        CP_ASYNC16(sbase + (arr ? AQ_LO : AQ_HI) + r * 144 + c * 16, g);
    }
    CP_COMMIT();
    // --- issue K/V tile 0 (group 1)
    attn_load_kv(qkvh, qkvl, sbase + AKV0, b * SEQ, D_MODEL + qcol, tid);
    CP_COMMIT();

    CP_WAIT1();            // Q ready
    __syncthreads();

    // preload Q-hi A fragments (4 k-steps)
    const uint32_t qh_addr = sbase + AQ_HI + (uint32_t)((wm * 16 + (lid & 15)) * 144)
                             + (uint32_t)((lid >> 4) * 16);
    const uint32_t ql_addr = sbase + AQ_LO + (uint32_t)((wm * 16 + (lid & 15)) * 144)
                             + (uint32_t)((lid >> 4) * 16);
    uint32_t aQh[4][4];
    #pragma unroll
    for (int ks = 0; ks < 4; ks++) LDSM4(aQh[ks], qh_addr + ks * 32);

    // B-frag lane constants
    const int b_row = ((lid >> 4) << 3) + (lid & 7);
    const int b_cs  = (lid >> 3) & 1;
    const int v_row = ((lid >> 3) & 1) * 8 + (lid & 7);
    const int v_col = (lid >> 4) * 8;

    const int row0 = q0 + wm * 16 + (lid >> 2);
    const int row1 = row0 + 8;

    float O[8][4];
    #pragma unroll
    for (int t = 0; t < 8; t++)
        #pragma unroll
        for (int k = 0; k < 4; k++) O[t][k] = 0.f;
    float m0r = -1e30f, m1r = -1e30f, l0r = 0.f, l1r = 0.f;

    for (int kt = 0; kt < nkt; kt++) {
        if (kt + 1 < nkt) {
            attn_load_kv(qkvh, qkvl,
                         sbase + AKV0 + ((kt + 1) & 1) * KV_STAGE,
                         b * SEQ + (kt + 1) * 64, D_MODEL + qcol, tid);
            CP_COMMIT();
            CP_WAIT1();
        } else {
            CP_WAIT0();
        }
        __syncthreads();

        const uint32_t stg = sbase + AKV0 + (kt & 1) * KV_STAGE;

        // ---- S = Q K^T (split x3)
        float S[8][4];
        #pragma unroll
        for (int t = 0; t < 8; t++)
            #pragma unroll
            for (int k = 0; k < 4; k++) S[t][k] = 0.f;

        #pragma unroll
        for (int ks = 0; ks < 4; ks++) {
            uint32_t aql[4];
            LDSM4(aql, ql_addr + ks * 32);
            const uint32_t kof = (uint32_t)((ks * 2 + b_cs) * 16);
            #pragma unroll
            for (int g = 0; g < 4; g++) {
                uint32_t kh[4], kl[4];
                uint32_t ka = stg + A_KH + (uint32_t)((g * 16 + b_row) * 144) + kof;
                LDSM4(kh, ka);
                LDSM4(kl, ka + (A_KL - A_KH));
                MMA16816(S[2 * g + 0], aQh[ks], kh[0], kh[1]);
                MMA16816(S[2 * g + 1], aQh[ks], kh[2], kh[3]);
                MMA16816(S[2 * g + 0], aQh[ks], kl[0], kl[1]);
                MMA16816(S[2 * g + 1], aQh[ks], kl[2], kl[3]);
                MMA16816(S[2 * g + 0], aql, kh[0], kh[1]);
                MMA16816(S[2 * g + 1], aql, kh[2], kh[3]);
            }
        }

        // ---- scale + causal mask + row max
        const int ktbase = kt * 64;
        const bool need_mask = (ktbase + 63) > (q0 + wm * 16);
        float vmax0 = -1e30f, vmax1 = -1e30f;
        #pragma unroll
        for (int t = 0; t < 8; t++) {
            float s0 = S[t][0] * SCALE, s1 = S[t][1] * SCALE;
            float s2 = S[t][2] * SCALE, s3 = S[t][3] * SCALE;
            if (need_mask) {
                int c0 = ktbase + t * 8 + (lid & 3) * 2;
                if (c0     > row0) s0 = -1e9f;
                if (c0 + 1 > row0) s1 = -1e9f;
                if (c0     > row1) s2 = -1e9f;
                if (c0 + 1 > row1) s3 = -1e9f;
            }
            S[t][0] = s0; S[t][1] = s1; S[t][2] = s2; S[t][3] = s3;
            vmax0 = fmaxf(vmax0, fmaxf(s0, s1));
            vmax1 = fmaxf(vmax1, fmaxf(s2, s3));
        }
        vmax0 = fmaxf(vmax0, __shfl_xor_sync(0xffffffffu, vmax0, 1));
        vmax0 = fmaxf(vmax0, __shfl_xor_sync(0xffffffffu, vmax0, 2));
        vmax1 = fmaxf(vmax1, __shfl_xor_sync(0xffffffffu, vmax1, 1));
        vmax1 = fmaxf(vmax1, __shfl_xor_sync(0xffffffffu, vmax1, 2));

        const float mn0 = fmaxf(m0r, vmax0);
        const float mn1 = fmaxf(m1r, vmax1);
        const float a0 = __expf(m0r - mn0);
        const float a1 = __expf(m1r - mn1);
        m0r = mn0; m1r = mn1;

        float ps0 = 0.f, ps1 = 0.f;
        #pragma unroll
        for (int t = 0; t < 8; t++) {
            S[t][0] = __expf(S[t][0] - mn0);
            S[t][1] = __expf(S[t][1] - mn0);
            S[t][2] = __expf(S[t][2] - mn1);
            S[t][3] = __expf(S[t][3] - mn1);
            ps0 += S[t][0] + S[t][1];
            ps1 += S[t][2] + S[t][3];
        }
        ps0 += __shfl_xor_sync(0xffffffffu, ps0, 1);
        ps0 += __shfl_xor_sync(0xffffffffu, ps0, 2);
        ps1 += __shfl_xor_sync(0xffffffffu, ps1, 1);
        ps1 += __shfl_xor_sync(0xffffffffu, ps1, 2);
        l0r = l0r * a0 + ps0;
        l1r = l1r * a1 + ps1;

        #pragma unroll
        for (int t = 0; t < 8; t++) {
            O[t][0] *= a0; O[t][1] *= a0;
            O[t][2] *= a1; O[t][3] *= a1;
        }

        // ---- P fragments (in-register C->A layout conversion), hi/lo split
        uint32_t aPh[4][4], aPl[4][4];
        #pragma unroll
        for (int ks = 0; ks < 4; ks++) {
            split2(S[2 * ks][0],     S[2 * ks][1],     aPh[ks][0], aPl[ks][0]);
            split2(S[2 * ks][2],     S[2 * ks][3],     aPh[ks][1], aPl[ks][1]);
            split2(S[2 * ks + 1][0], S[2 * ks + 1][1], aPh[ks][2], aPl[ks][2]);
            split2(S[2 * ks + 1][2], S[2 * ks + 1][3], aPh[ks][3], aPl[ks][3]);
        }

        // ---- O += P V  (split x3), V^T via ldmatrix.trans
        #pragma unroll
        for (int ks = 0; ks < 4; ks++) {
            #pragma unroll
            for (int g = 0; g < 4; g++) {
                uint32_t vh[4], vl[4];
                uint32_t va = stg + A_VH + (uint32_t)((ks * 16 + v_row) * 144)
                              + (uint32_t)((v_col + g * 16) * 2);
                LDSM4T(vh, va);
                LDSM4T(vl, va + (A_VL - A_VH));
                MMA16816(O[2 * g + 0], aPh[ks], vh[0], vh[1]);
                MMA16816(O[2 * g + 1], aPh[ks], vh[2], vh[3]);
                MMA16816(O[2 * g + 0], aPh[ks], vl[0], vl[1]);
                MMA16816(O[2 * g + 1], aPh[ks], vl[2], vl[3]);
                MMA16816(O[2 * g + 0], aPl[ks], vh[0], vh[1]);
                MMA16816(O[2 * g + 1], aPl[ks], vh[2], vh[3]);
            }
        }
        __syncthreads();
    }

    // ---- epilogue: normalize, split to bf16 hi/lo, store [4096,1024]
    const float inv0 = 1.f / l0r;
    const float inv1 = 1.f / l1r;
    const int gr0 = b * SEQ + row0;
    const int gr1 = b * SEQ + row1;
    #pragma unroll
    for (int t = 0; t < 8; t++) {
        int col = qcol + t * 8 + (lid & 3) * 2;
        uint32_t hh, ll;
        split2(O[t][0] * inv0, O[t][1] * inv0, hh, ll);
        *(uint32_t*)(outh + (size_t)gr0 * D_MODEL + col) = hh;
        *(uint32_t*)(outl + (size_t)gr0 * D_MODEL + col) = ll;
        split2(O[t][2] * inv1, O[t][3] * inv1, hh, ll);
        *(uint32_t*)(outh + (size_t)gr1 * D_MODEL + col) = hh;
        *(uint32_t*)(outl + (size_t)gr1 * D_MODEL + col) = ll;
    }
}

// ---------------------------------------------------------------------------
extern "C" void kernel_launch(void* const* d_in, const int* in_sizes, int n_in,
                              void* d_out, int out_size)
{
    const float* query = (const float*)d_in[0];
    const float* w_qkv = (const float*)d_in[4];
    const float* w_o   = (const float*)d_in[5];
    float* out = (float*)d_out;

    __nv_bfloat16 *Ahi, *Alo, *QKVhi, *QKVlo, *W1hi, *W1lo, *W2hi, *W2lo;
    cudaGetSymbolAddress((void**)&Ahi,   g_Ahi);
    cudaGetSymbolAddress((void**)&Alo,   g_Alo);
    cudaGetSymbolAddress((void**)&QKVhi, g_QKVhi);
    cudaGetSymbolAddress((void**)&QKVlo, g_QKVlo);
    cudaGetSymbolAddress((void**)&W1hi,  g_W1hi);
    cudaGetSymbolAddress((void**)&W1lo,  g_W1lo);
    cudaGetSymbolAddress((void**)&W2hi,  g_W2hi);
    cudaGetSymbolAddress((void**)&W2lo,  g_W2lo);

    cudaFuncSetAttribute(gemm_hmma_kernel<true>,
                         cudaFuncAttributeMaxDynamicSharedMemorySize, GEMM_SMEM);
    cudaFuncSetAttribute(gemm_hmma_kernel<false>,
                         cudaFuncAttributeMaxDynamicSharedMemorySize, GEMM_SMEM);
    cudaFuncSetAttribute(attn_hmma_kernel,
                         cudaFuncAttributeMaxDynamicSharedMemorySize, ATTN_SMEM);

    // Prep
    {
        dim3 blk(32, 8);
        transpose_split_kernel<<<dim3(3 * D_MODEL / 32, D_MODEL / 32), blk>>>(
            w_qkv, W1hi, W1lo, D_MODEL, 3 * D_MODEL);
        transpose_split_kernel<<<dim3(D_MODEL / 32, D_MODEL / 32), blk>>>(
            w_o, W2hi, W2lo, D_MODEL, D_MODEL);
        int n4 = M_ROWS * D_MODEL / 4;
        split_f32_kernel<<<(n4 + 255) / 256, 256>>>(query, Ahi, Alo, n4);
    }

    // 1) qkv = query @ w_qkv -> bf16 hi/lo split directly
    gemm_hmma_kernel<true><<<dim3(3 * D_MODEL / 128, M_ROWS / 128), 256, GEMM_SMEM>>>(
        Ahi, Alo, W1hi, W1lo, nullptr, QKVhi, QKVlo, M_ROWS, 3 * D_MODEL, D_MODEL);

    // 2) causal flash attention -> ctx split (reuses Ahi/Alo)
    attn_hmma_kernel<<<dim3(SEQ / 128, BATCH * N_HEADS), 256, ATTN_SMEM>>>(
        QKVhi, QKVlo, Ahi, Alo);

    // 3) out = ctx @ w_o -> fp32
    gemm_hmma_kernel<false><<<dim3(D_MODEL / 128, M_ROWS / 128), 256, GEMM_SMEM>>>(
        Ahi, Alo, W2hi, W2lo, out, nullptr, nullptr, M_ROWS, D_MODEL, D_MODEL);
}

// round 5
// speedup vs baseline: 5.5950x; 1.5723x over previous
#include <cuda_runtime.h>
#include <cuda_fp16.h>
#include <math.h>
#include <cstdint>

#define D_MODEL 1024
#define N_HEADS 16
#define D_K     64
#define BATCH   2
#define SEQ     2048
#define SCALE   0.125f  /* 1/sqrt(64) */
#define M_ROWS  (BATCH * SEQ)   /* 4096 */

// ---------------------------------------------------------------------------
// Scratch (allocation-free rule: __device__ globals)
// ---------------------------------------------------------------------------
__device__ __half g_A16[(size_t)M_ROWS * D_MODEL];          // query as fp16
__device__ __half g_ctx16[(size_t)M_ROWS * D_MODEL];        // attention output fp16
__device__ __half g_QKVh[(size_t)M_ROWS * 3 * D_MODEL];     // qkv hi fp16
__device__ __half g_QKVl[(size_t)M_ROWS * 3 * D_MODEL];     // qkv lo fp16 (V correction)
__device__ __half g_W1h[(size_t)3 * D_MODEL * D_MODEL];     // w_qkv^T [3072,1024] hi
__device__ __half g_W1l[(size_t)3 * D_MODEL * D_MODEL];     // lo
__device__ __half g_W2h[(size_t)D_MODEL * D_MODEL];         // w_o^T [1024,1024] hi
__device__ __half g_W2l[(size_t)D_MODEL * D_MODEL];         // lo

// ---------------------------------------------------------------------------
// Helpers
// ---------------------------------------------------------------------------
__device__ __forceinline__ uint32_t smem_u32(const void* p) {
    uint32_t a;
    asm("{ .reg .u64 t; cvta.to.shared.u64 t, %1; cvt.u32.u64 %0, t; }"
        : "=r"(a) : "l"(p));
    return a;
}

#define CP_ASYNC16(saddr, gptr) \
    asm volatile("cp.async.cg.shared.global [%0], [%1], 16;" :: "r"(saddr), "l"(gptr))
#define CP_COMMIT() asm volatile("cp.async.commit_group;")
#define CP_WAIT1()  asm volatile("cp.async.wait_group 1;")
#define CP_WAIT0()  asm volatile("cp.async.wait_group 0;")

#define LDSM4(r, addr) \
    asm volatile("ldmatrix.sync.aligned.m8n8.x4.shared.b16 {%0,%1,%2,%3}, [%4];" \
        : "=r"((r)[0]), "=r"((r)[1]), "=r"((r)[2]), "=r"((r)[3]) : "r"(addr))
#define LDSM4T(r, addr) \
    asm volatile("ldmatrix.sync.aligned.m8n8.x4.trans.shared.b16 {%0,%1,%2,%3}, [%4];" \
        : "=r"((r)[0]), "=r"((r)[1]), "=r"((r)[2]), "=r"((r)[3]) : "r"(addr))

#define MMA16816(d, a, b0, b1) \
    asm volatile("mma.sync.aligned.m16n8k16.row.col.f32.f16.f16.f32 " \
        "{%0,%1,%2,%3}, {%4,%5,%6,%7}, {%8,%9}, {%0,%1,%2,%3};" \
        : "+f"((d)[0]), "+f"((d)[1]), "+f"((d)[2]), "+f"((d)[3]) \
        : "r"((a)[0]), "r"((a)[1]), "r"((a)[2]), "r"((a)[3]), "r"(b0), "r"(b1))

__device__ __forceinline__ uint32_t packh2(float x, float y) {
    __half2 h = __floats2half2_rn(x, y);
    return *(uint32_t*)&h;
}
// split two fp32 into fp16 hi pair + fp16 lo pair (packed u32)
__device__ __forceinline__ void split2h(float x, float y, uint32_t& h, uint32_t& l) {
    __half2 hh = __floats2half2_rn(x, y);
    float2 hf = __half22float2(hh);
    __half2 ll = __floats2half2_rn(x - hf.x, y - hf.y);
    h = *(uint32_t*)&hh;
    l = *(uint32_t*)&ll;
}

// ---------------------------------------------------------------------------
// Prep kernels
// ---------------------------------------------------------------------------
__global__ void tohalf_kernel(const float* __restrict__ x,
                              __half* __restrict__ y, int n4) {
    int i = blockIdx.x * blockDim.x + threadIdx.x;
    if (i >= n4) return;
    float4 v = ((const float4*)x)[i];
    *(uint2*)(y + (size_t)i * 4) = make_uint2(packh2(v.x, v.y), packh2(v.z, v.w));
}

// W [K,N] fp32 row-major -> T_hi/T_lo [N,K] fp16 row-major
__global__ void transpose_split_kernel(const float* __restrict__ W,
                                       __half* __restrict__ Thi,
                                       __half* __restrict__ Tlo,
                                       int K, int N) {
    __shared__ float t[32][33];
    int n0 = blockIdx.x * 32, k0 = blockIdx.y * 32;
    int tx = threadIdx.x, ty = threadIdx.y;
    #pragma unroll
    for (int i = ty; i < 32; i += 8)
        t[i][tx] = W[(size_t)(k0 + i) * N + n0 + tx];
    __syncthreads();
    #pragma unroll
    for (int i = ty; i < 32; i += 8) {
        float v = t[tx][i];
        __half h = __float2half_rn(v);
        size_t o = (size_t)(n0 + i) * K + k0 + tx;
        Thi[o] = h;
        Tlo[o] = __float2half_rn(v - __half2float(h));
    }
}

// ---------------------------------------------------------------------------
// HMMA fp16x2 GEMM: C = A16[M,K] @ (Wh + Wl)[N,K]^T
// CTA 128x128, BK=64, 8 warps (2x4), 2-stage cp.async, 96KB smem -> 2 CTA/SM.
// ---------------------------------------------------------------------------
#define TILE_BYTES  (128 * 128)
#define STAGE_BYTES (3 * TILE_BYTES)   /* 49152 */
#define SM_A   0
#define SM_B_H TILE_BYTES
#define SM_B_L (2 * TILE_BYTES)
#define GEMM_SMEM (2 * STAGE_BYTES)    /* 98304 */

template <bool SPLIT_OUT>
__global__ void __launch_bounds__(256, 2) gemm_hmma_kernel(
    const __half* __restrict__ A16,
    const __half* __restrict__ Bh, const __half* __restrict__ Bl,
    float* __restrict__ C,
    __half* __restrict__ Chi, __half* __restrict__ Clo,
    int M, int N, int K)
{
    extern __shared__ char smem[];
    const uint32_t sbase = smem_u32(smem);
    const int tid = threadIdx.x;
    const int lid = tid & 31;
    const int wid = tid >> 5;
    const int wm  = wid >> 2;
    const int wn  = wid & 3;
    const int m0 = blockIdx.y * 128;
    const int n0 = blockIdx.x * 128;

    const int cr = tid >> 3;
    const int cc = tid & 7;
    const uint32_t csw = (uint32_t)((cc ^ (cr & 7)) << 4);

    const int niter = K / 64;

    {
        uint32_t sb = sbase;
        #pragma unroll
        for (int u = 0; u < 4; u++) {
            int r = cr + u * 32;
            uint32_t so = (uint32_t)(r * 128) + csw;
            size_t ga = (size_t)(m0 + r) * K + cc * 8;
            size_t gb = (size_t)(n0 + r) * K + cc * 8;
            CP_ASYNC16(sb + SM_A + so, A16 + ga);
            CP_ASYNC16(sb + SM_B_H + so, Bh + gb);
            CP_ASYNC16(sb + SM_B_L + so, Bl + gb);
        }
        CP_COMMIT();
    }

    float acc[4][4][4];
    #pragma unroll
    for (int i = 0; i < 4; i++)
        #pragma unroll
        for (int j = 0; j < 4; j++)
            #pragma unroll
            for (int k = 0; k < 4; k++) acc[i][j][k] = 0.f;

    const int a_rowlane = lid & 15;
    const int a_csel    = lid >> 4;
    const int b_rowlane = ((lid >> 4) << 3) + (lid & 7);
    const int b_csel    = (lid >> 3) & 1;
    const int sw_lane   = lid & 7;

    for (int kt = 0; kt < niter; kt++) {
        if (kt + 1 < niter) {
            const int kofs = (kt + 1) * 64;
            uint32_t sb = sbase + ((kt + 1) & 1) * STAGE_BYTES;
            #pragma unroll
            for (int u = 0; u < 4; u++) {
                int r = cr + u * 32;
                uint32_t so = (uint32_t)(r * 128) + csw;
                size_t ga = (size_t)(m0 + r) * K + kofs + cc * 8;
                size_t gb = (size_t)(n0 + r) * K + kofs + cc * 8;
                CP_ASYNC16(sb + SM_A + so, A16 + ga);
                CP_ASYNC16(sb + SM_B_H + so, Bh + gb);
                CP_ASYNC16(sb + SM_B_L + so, Bl + gb);
            }
            CP_COMMIT();
            CP_WAIT1();
        } else {
            CP_WAIT0();
        }
        __syncthreads();

        const uint32_t sb = sbase + (kt & 1) * STAGE_BYTES;
        const uint32_t abase0 = sb + SM_A + (uint32_t)((wm * 64 + a_rowlane) * 128);
        const uint32_t bbase0 = sb + SM_B_H + (uint32_t)((wn * 32 + b_rowlane) * 128);

        #pragma unroll
        for (int ks = 0; ks < 4; ks++) {
            const uint32_t axor = (uint32_t)(((ks * 2 + a_csel) ^ sw_lane) << 4);
            const uint32_t bxor = (uint32_t)(((ks * 2 + b_csel) ^ sw_lane) << 4);
            const uint32_t abase = abase0 + axor;
            const uint32_t bbase = bbase0 + bxor;

            uint32_t a[4][4], bh[2][4], bl[2][4];
            #pragma unroll
            for (int tm = 0; tm < 4; tm++) LDSM4(a[tm], abase + tm * 2048);
            #pragma unroll
            for (int tg = 0; tg < 2; tg++) LDSM4(bh[tg], bbase + tg * 2048);
            #pragma unroll
            for (int tg = 0; tg < 2; tg++) LDSM4(bl[tg], bbase + TILE_BYTES + tg * 2048);

            #pragma unroll
            for (int tm = 0; tm < 4; tm++) {
                #pragma unroll
                for (int tg = 0; tg < 2; tg++) {
                    MMA16816(acc[tm][tg * 2 + 0], a[tm], bh[tg][0], bh[tg][1]);
                    MMA16816(acc[tm][tg * 2 + 1], a[tm], bh[tg][2], bh[tg][3]);
                    MMA16816(acc[tm][tg * 2 + 0], a[tm], bl[tg][0], bl[tg][1]);
                    MMA16816(acc[tm][tg * 2 + 1], a[tm], bl[tg][2], bl[tg][3]);
                }
            }
        }
        __syncthreads();
    }

    const int erow = (lid >> 2);
    const int ecol = (lid & 3) * 2;
    #pragma unroll
    for (int tm = 0; tm < 4; tm++) {
        #pragma unroll
        for (int tg = 0; tg < 4; tg++) {
            int row = m0 + wm * 64 + tm * 16 + erow;
            int col = n0 + wn * 32 + tg * 8 + ecol;
            if (SPLIT_OUT) {
                uint32_t h, l;
                split2h(acc[tm][tg][0], acc[tm][tg][1], h, l);
                *(uint32_t*)(Chi + (size_t)row * N + col) = h;
                *(uint32_t*)(Clo + (size_t)row * N + col) = l;
                split2h(acc[tm][tg][2], acc[tm][tg][3], h, l);
                *(uint32_t*)(Chi + (size_t)(row + 8) * N + col) = h;
                *(uint32_t*)(Clo + (size_t)(row + 8) * N + col) = l;
            } else {
                *(float2*)(C + (size_t)row * N + col) =
                    make_float2(acc[tm][tg][0], acc[tm][tg][1]);
                *(float2*)(C + (size_t)(row + 8) * N + col) =
                    make_float2(acc[tm][tg][2], acc[tm][tg][3]);
            }
        }
    }
}

// ---------------------------------------------------------------------------
// HMMA flash attention (causal), fp16: S = Q16 K16 (1 term),
// PV = P16 (Vh + Vl) (2 terms). 128 q-rows/CTA, K-tile 64, 2-stage cp.async.
// Smem: Q 128x144B + 2 stages x (K,Vh,Vl) 64x144B = 72KB -> 2 CTA/SM.
// ---------------------------------------------------------------------------
#define AQ    0
#define AKV0  (128 * 144)              /* 18432 */
#define KV_STAGE (3 * 64 * 144)        /* 27648 */
#define A_KH 0
#define A_VH (64 * 144)
#define A_VL (2 * 64 * 144)
#define ATTN_SMEM (AKV0 + 2 * KV_STAGE) /* 73728 */

__device__ __forceinline__ void attn_load_kv(
    const __half* __restrict__ qh, const __half* __restrict__ ql,
    uint32_t dst, int grow0, int kcol, int tid)
{
    #pragma unroll
    for (int u = 0; u < 6; u++) {
        int piece = u >> 1;                       // 0:K 1:VH 2:VL
        int r = (u & 1) * 32 + (tid >> 3);
        int c = tid & 7;
        const __half* src = (piece == 2) ? ql : qh;
        int col = kcol + ((piece >= 1) ? D_MODEL : 0) + c * 8;
        const __half* g = src + (size_t)(grow0 + r) * 3072 + col;
        CP_ASYNC16(dst + piece * (64 * 144) + r * 144 + c * 16, g);
    }
}

__global__ void __launch_bounds__(256, 2) attn_hmma_kernel(
    const __half* __restrict__ qkvh, const __half* __restrict__ qkvl,
    __half* __restrict__ ctx16)
{
    extern __shared__ char smem[];
    const uint32_t sbase = smem_u32(smem);
    const int tid = threadIdx.x;
    const int lid = tid & 31;
    const int wm  = tid >> 5;

    const int qb = (int)gridDim.x - 1 - (int)blockIdx.x;  // big tiles first
    const int bh = blockIdx.y;
    const int b  = bh >> 4;
    const int h  = bh & 15;
    const int q0 = qb * 128;
    const int nkt = qb * 2 + 2;

    const int qcol = h * D_K;
    const int browQ = b * SEQ + q0;

    // --- issue Q loads (group 0)
    #pragma unroll
    for (int u = 0; u < 4; u++) {
        int r = u * 32 + (tid >> 3);
        int c = tid & 7;
        const __half* g = qkvh + (size_t)(browQ + r) * 3072 + qcol + c * 8;
        CP_ASYNC16(sbase + AQ + r * 144 + c * 16, g);
    }
    CP_COMMIT();
    // --- issue K/V tile 0 (group 1)
    attn_load_kv(qkvh, qkvl, sbase + AKV0, b * SEQ, D_MODEL + qcol, tid);
    CP_COMMIT();

    CP_WAIT1();            // Q ready
    __syncthreads();

    // preload Q A-fragments (4 k-steps)
    const uint32_t q_addr = sbase + AQ + (uint32_t)((wm * 16 + (lid & 15)) * 144)
                            + (uint32_t)((lid >> 4) * 16);
    uint32_t aQ[4][4];
    #pragma unroll
    for (int ks = 0; ks < 4; ks++) LDSM4(aQ[ks], q_addr + ks * 32);

    // B-frag lane constants
    const int b_row = ((lid >> 4) << 3) + (lid & 7);
    const int b_cs  = (lid >> 3) & 1;
    const int v_row = ((lid >> 3) & 1) * 8 + (lid & 7);
    const int v_col = (lid >> 4) * 8;

    const int row0 = q0 + wm * 16 + (lid >> 2);
    const int row1 = row0 + 8;

    float O[8][4];
    #pragma unroll
    for (int t = 0; t < 8; t++)
        #pragma unroll
        for (int k = 0; k < 4; k++) O[t][k] = 0.f;
    float m0r = -1e30f, m1r = -1e30f, l0r = 0.f, l1r = 0.f;

    for (int kt = 0; kt < nkt; kt++) {
        if (kt + 1 < nkt) {
            attn_load_kv(qkvh, qkvl,
                         sbase + AKV0 + ((kt + 1) & 1) * KV_STAGE,
                         b * SEQ + (kt + 1) * 64, D_MODEL + qcol, tid);
            CP_COMMIT();
            CP_WAIT1();
        } else {
            CP_WAIT0();
        }
        __syncthreads();

        const uint32_t stg = sbase + AKV0 + (kt & 1) * KV_STAGE;

        // ---- S = Q K^T (single fp16 term)
        float S[8][4];
        #pragma unroll
        for (int t = 0; t < 8; t++)
            #pragma unroll
            for (int k = 0; k < 4; k++) S[t][k] = 0.f;

        #pragma unroll
        for (int ks = 0; ks < 4; ks++) {
            const uint32_t kof = (uint32_t)((ks * 2 + b_cs) * 16);
            #pragma unroll
            for (int g = 0; g < 4; g++) {
                uint32_t kh[4];
                LDSM4(kh, stg + A_KH + (uint32_t)((g * 16 + b_row) * 144) + kof);
                MMA16816(S[2 * g + 0], aQ[ks], kh[0], kh[1]);
                MMA16816(S[2 * g + 1], aQ[ks], kh[2], kh[3]);
            }
        }

        // ---- scale + causal mask + row max
        const int ktbase = kt * 64;
        const bool need_mask = (ktbase + 63) > (q0 + wm * 16);
        float vmax0 = -1e30f, vmax1 = -1e30f;
        #pragma unroll
        for (int t = 0; t < 8; t++) {
            float s0 = S[t][0] * SCALE, s1 = S[t][1] * SCALE;
            float s2 = S[t][2] * SCALE, s3 = S[t][3] * SCALE;
            if (need_mask) {
                int c0 = ktbase + t * 8 + (lid & 3) * 2;
                if (c0     > row0) s0 = -1e9f;
                if (c0 + 1 > row0) s1 = -1e9f;
                if (c0     > row1) s2 = -1e9f;
                if (c0 + 1 > row1) s3 = -1e9f;
            }
            S[t][0] = s0; S[t][1] = s1; S[t][2] = s2; S[t][3] = s3;
            vmax0 = fmaxf(vmax0, fmaxf(s0, s1));
            vmax1 = fmaxf(vmax1, fmaxf(s2, s3));
        }
        vmax0 = fmaxf(vmax0, __shfl_xor_sync(0xffffffffu, vmax0, 1));
        vmax0 = fmaxf(vmax0, __shfl_xor_sync(0xffffffffu, vmax0, 2));
        vmax1 = fmaxf(vmax1, __shfl_xor_sync(0xffffffffu, vmax1, 1));
        vmax1 = fmaxf(vmax1, __shfl_xor_sync(0xffffffffu, vmax1, 2));

        const float mn0 = fmaxf(m0r, vmax0);
        const float mn1 = fmaxf(m1r, vmax1);
        const float a0 = __expf(m0r - mn0);
        const float a1 = __expf(m1r - mn1);
        m0r = mn0; m1r = mn1;

        float ps0 = 0.f, ps1 = 0.f;
        #pragma unroll
        for (int t = 0; t < 8; t++) {
            S[t][0] = __expf(S[t][0] - mn0);
            S[t][1] = __expf(S[t][1] - mn0);
            S[t][2] = __expf(S[t][2] - mn1);
            S[t][3] = __expf(S[t][3] - mn1);
            ps0 += S[t][0] + S[t][1];
            ps1 += S[t][2] + S[t][3];
        }
        ps0 += __shfl_xor_sync(0xffffffffu, ps0, 1);
        ps0 += __shfl_xor_sync(0xffffffffu, ps0, 2);
        ps1 += __shfl_xor_sync(0xffffffffu, ps1, 1);
        ps1 += __shfl_xor_sync(0xffffffffu, ps1, 2);
        l0r = l0r * a0 + ps0;
        l1r = l1r * a1 + ps1;

        #pragma unroll
        for (int t = 0; t < 8; t++) {
            O[t][0] *= a0; O[t][1] *= a0;
            O[t][2] *= a1; O[t][3] *= a1;
        }

        // ---- P fragments (fp16 single, C->A layout conversion in registers)
        uint32_t aP[4][4];
        #pragma unroll
        for (int ks = 0; ks < 4; ks++) {
            aP[ks][0] = packh2(S[2 * ks][0],     S[2 * ks][1]);
            aP[ks][1] = packh2(S[2 * ks][2],     S[2 * ks][3]);
            aP[ks][2] = packh2(S[2 * ks + 1][0], S[2 * ks + 1][1]);
            aP[ks][3] = packh2(S[2 * ks + 1][2], S[2 * ks + 1][3]);
        }

        // ---- O += P (Vh + Vl), V^T via ldmatrix.trans
        #pragma unroll
        for (int ks = 0; ks < 4; ks++) {
            #pragma unroll
            for (int g = 0; g < 4; g++) {
                uint32_t vh[4], vl[4];
                uint32_t va = stg + A_VH + (uint32_t)((ks * 16 + v_row) * 144)
                              + (uint32_t)((v_col + g * 16) * 2);
                LDSM4T(vh, va);
                LDSM4T(vl, va + (A_VL - A_VH));
                MMA16816(O[2 * g + 0], aP[ks], vh[0], vh[1]);
                MMA16816(O[2 * g + 1], aP[ks], vh[2], vh[3]);
                MMA16816(O[2 * g + 0], aP[ks], vl[0], vl[1]);
                MMA16816(O[2 * g + 1], aP[ks], vl[2], vl[3]);
            }
        }
        __syncthreads();
    }

    // ---- epilogue: normalize, fp16 pack, store ctx16 [4096,1024]
    const float inv0 = 1.f / l0r;
    const float inv1 = 1.f / l1r;
    const int gr0 = b * SEQ + row0;
    const int gr1 = b * SEQ + row1;
    #pragma unroll
    for (int t = 0; t < 8; t++) {
        int col = qcol + t * 8 + (lid & 3) * 2;
        *(uint32_t*)(ctx16 + (size_t)gr0 * D_MODEL + col) =
            packh2(O[t][0] * inv0, O[t][1] * inv0);
        *(uint32_t*)(ctx16 + (size_t)gr1 * D_MODEL + col) =
            packh2(O[t][2] * inv1, O[t][3] * inv1);
    }
}

// ---------------------------------------------------------------------------
extern "C" void kernel_launch(void* const* d_in, const int* in_sizes, int n_in,
                              void* d_out, int out_size)
{
    const float* query = (const float*)d_in[0];
    const float* w_qkv = (const float*)d_in[4];
    const float* w_o   = (const float*)d_in[5];
    float* out = (float*)d_out;

    __half *A16, *ctx16, *QKVh, *QKVl, *W1h, *W1l, *W2h, *W2l;
    cudaGetSymbolAddress((void**)&A16,   g_A16);
    cudaGetSymbolAddress((void**)&ctx16, g_ctx16);
    cudaGetSymbolAddress((void**)&QKVh,  g_QKVh);
    cudaGetSymbolAddress((void**)&QKVl,  g_QKVl);
    cudaGetSymbolAddress((void**)&W1h,   g_W1h);
    cudaGetSymbolAddress((void**)&W1l,   g_W1l);
    cudaGetSymbolAddress((void**)&W2h,   g_W2h);
    cudaGetSymbolAddress((void**)&W2l,   g_W2l);

    cudaFuncSetAttribute(gemm_hmma_kernel<true>,
                         cudaFuncAttributeMaxDynamicSharedMemorySize, GEMM_SMEM);
    cudaFuncSetAttribute(gemm_hmma_kernel<false>,
                         cudaFuncAttributeMaxDynamicSharedMemorySize, GEMM_SMEM);
    cudaFuncSetAttribute(attn_hmma_kernel,
                         cudaFuncAttributeMaxDynamicSharedMemorySize, ATTN_SMEM);

    // Prep
    {
        dim3 blk(32, 8);
        transpose_split_kernel<<<dim3(3 * D_MODEL / 32, D_MODEL / 32), blk>>>(
            w_qkv, W1h, W1l, D_MODEL, 3 * D_MODEL);
        transpose_split_kernel<<<dim3(D_MODEL / 32, D_MODEL / 32), blk>>>(
            w_o, W2h, W2l, D_MODEL, D_MODEL);
        int n4 = M_ROWS * D_MODEL / 4;
        tohalf_kernel<<<(n4 + 255) / 256, 256>>>(query, A16, n4);
    }

    // 1) qkv = query @ w_qkv -> fp16 hi/lo split
    gemm_hmma_kernel<true><<<dim3(3 * D_MODEL / 128, M_ROWS / 128), 256, GEMM_SMEM>>>(
        A16, W1h, W1l, nullptr, QKVh, QKVl, M_ROWS, 3 * D_MODEL, D_MODEL);

    // 2) causal flash attention -> ctx fp16
    attn_hmma_kernel<<<dim3(SEQ / 128, BATCH * N_HEADS), 256, ATTN_SMEM>>>(
        QKVh, QKVl, ctx16);

    // 3) out = ctx @ w_o -> fp32
    gemm_hmma_kernel<false><<<dim3(D_MODEL / 128, M_ROWS / 128), 256, GEMM_SMEM>>>(
        ctx16, W2h, W2l, out, nullptr, nullptr, M_ROWS, D_MODEL, D_MODEL);
}

// round 6
// speedup vs baseline: 8.5871x; 1.5348x over previous
#include <cuda_runtime.h>
#include <cuda_fp16.h>
#include <math.h>
#include <cstdint>

#define D_MODEL 1024
#define N_HEADS 16
#define D_K     64
#define BATCH   2
#define SEQ     2048
#define SCALE   0.125f  /* 1/sqrt(64) */
#define M_ROWS  (BATCH * SEQ)   /* 4096 */

// ---------------------------------------------------------------------------
// Scratch (allocation-free rule: __device__ globals)
// ---------------------------------------------------------------------------
__device__ __half g_A16[(size_t)M_ROWS * D_MODEL];          // query as fp16
__device__ __half g_ctx16[(size_t)M_ROWS * D_MODEL];        // attention output fp16
__device__ __half g_QKV[(size_t)M_ROWS * 3 * D_MODEL];      // qkv fp16
__device__ __half g_W1[(size_t)3 * D_MODEL * D_MODEL];      // w_qkv^T [3072,1024]
__device__ __half g_W2[(size_t)D_MODEL * D_MODEL];          // w_o^T [1024,1024]

// ---------------------------------------------------------------------------
// Helpers
// ---------------------------------------------------------------------------
__device__ __forceinline__ uint32_t smem_u32(const void* p) {
    uint32_t a;
    asm("{ .reg .u64 t; cvta.to.shared.u64 t, %1; cvt.u32.u64 %0, t; }"
        : "=r"(a) : "l"(p));
    return a;
}

#define CP_ASYNC16(saddr, gptr) \
    asm volatile("cp.async.cg.shared.global [%0], [%1], 16;" :: "r"(saddr), "l"(gptr))
#define CP_COMMIT() asm volatile("cp.async.commit_group;")
#define CP_WAIT2()  asm volatile("cp.async.wait_group 2;")
#define CP_WAIT1()  asm volatile("cp.async.wait_group 1;")
#define CP_WAIT0()  asm volatile("cp.async.wait_group 0;")

#define LDSM4(r, addr) \
    asm volatile("ldmatrix.sync.aligned.m8n8.x4.shared.b16 {%0,%1,%2,%3}, [%4];" \
        : "=r"((r)[0]), "=r"((r)[1]), "=r"((r)[2]), "=r"((r)[3]) : "r"(addr))
#define LDSM4T(r, addr) \
    asm volatile("ldmatrix.sync.aligned.m8n8.x4.trans.shared.b16 {%0,%1,%2,%3}, [%4];" \
        : "=r"((r)[0]), "=r"((r)[1]), "=r"((r)[2]), "=r"((r)[3]) : "r"(addr))

#define MMA16816(d, a, b0, b1) \
    asm volatile("mma.sync.aligned.m16n8k16.row.col.f32.f16.f16.f32 " \
        "{%0,%1,%2,%3}, {%4,%5,%6,%7}, {%8,%9}, {%0,%1,%2,%3};" \
        : "+f"((d)[0]), "+f"((d)[1]), "+f"((d)[2]), "+f"((d)[3]) \
        : "r"((a)[0]), "r"((a)[1]), "r"((a)[2]), "r"((a)[3]), "r"(b0), "r"(b1))

__device__ __forceinline__ uint32_t packh2(float x, float y) {
    __half2 h = __floats2half2_rn(x, y);
    return *(uint32_t*)&h;
}

// ---------------------------------------------------------------------------
// Prep kernels
// ---------------------------------------------------------------------------
__global__ void tohalf_kernel(const float* __restrict__ x,
                              __half* __restrict__ y, int n4) {
    int i = blockIdx.x * blockDim.x + threadIdx.x;
    if (i >= n4) return;
    float4 v = ((const float4*)x)[i];
    *(uint2*)(y + (size_t)i * 4) = make_uint2(packh2(v.x, v.y), packh2(v.z, v.w));
}

// W [K,N] fp32 row-major -> T [N,K] fp16 row-major
__global__ void transpose_half_kernel(const float* __restrict__ W,
                                      __half* __restrict__ T, int K, int N) {
    __shared__ float t[32][33];
    int n0 = blockIdx.x * 32, k0 = blockIdx.y * 32;
    int tx = threadIdx.x, ty = threadIdx.y;
    #pragma unroll
    for (int i = ty; i < 32; i += 8)
        t[i][tx] = W[(size_t)(k0 + i) * N + n0 + tx];
    __syncthreads();
    #pragma unroll
    for (int i = ty; i < 32; i += 8)
        T[(size_t)(n0 + i) * K + k0 + tx] = __float2half_rn(t[tx][i]);
}

// ---------------------------------------------------------------------------
// HMMA fp16 GEMM: C = A16[M,K] @ W[N,K]^T
// CTA 128x128, BK=64, 8 warps (2x4), 3-stage cp.async, 96KB smem -> 2 CTA/SM.
// ---------------------------------------------------------------------------
#define G_TILE   16384
#define G_STAGE  (2 * G_TILE)        /* 32768 */
#define GEMM_SMEM (3 * G_STAGE)      /* 98304 */

__device__ __forceinline__ void gemm_load(
    const __half* __restrict__ A, const __half* __restrict__ B,
    uint32_t sb, int m0, int n0, int K, int kofs, int tid)
{
    const int cr = tid >> 3;
    const int cc = tid & 7;
    const uint32_t csw = (uint32_t)((cc ^ (cr & 7)) << 4);
    #pragma unroll
    for (int u = 0; u < 4; u++) {
        int r = cr + u * 32;
        uint32_t so = (uint32_t)(r * 128) + csw;
        CP_ASYNC16(sb + so,          A + (size_t)(m0 + r) * K + kofs + cc * 8);
        CP_ASYNC16(sb + G_TILE + so, B + (size_t)(n0 + r) * K + kofs + cc * 8);
    }
    CP_COMMIT();
}

template <bool HALF_OUT>
__global__ void __launch_bounds__(256, 2) gemm_hmma_kernel(
    const __half* __restrict__ A16, const __half* __restrict__ B16,
    float* __restrict__ C, __half* __restrict__ Ch,
    int M, int N, int K)
{
    extern __shared__ char smem[];
    const uint32_t sbase = smem_u32(smem);
    const int tid = threadIdx.x;
    const int lid = tid & 31;
    const int wid = tid >> 5;
    const int wm  = wid >> 2;
    const int wn  = wid & 3;
    const int m0 = blockIdx.y * 128;
    const int n0 = blockIdx.x * 128;

    const int niter = K / 64;

    gemm_load(A16, B16, sbase,           m0, n0, K, 0,  tid);
    gemm_load(A16, B16, sbase + G_STAGE, m0, n0, K, 64, tid);

    float acc[4][4][4];
    #pragma unroll
    for (int i = 0; i < 4; i++)
        #pragma unroll
        for (int j = 0; j < 4; j++)
            #pragma unroll
            for (int k = 0; k < 4; k++) acc[i][j][k] = 0.f;

    const int a_rowlane = lid & 15;
    const int a_csel    = lid >> 4;
    const int b_rowlane = ((lid >> 4) << 3) + (lid & 7);
    const int b_csel    = (lid >> 3) & 1;
    const int sw_lane   = lid & 7;

    int stage = 0;
    for (int kt = 0; kt < niter; kt++) {
        if (kt + 2 < niter) {
            int ps = stage + 2; if (ps >= 3) ps -= 3;
            gemm_load(A16, B16, sbase + ps * G_STAGE, m0, n0, K, (kt + 2) * 64, tid);
            CP_WAIT2();
        } else if (kt == niter - 2) {
            CP_WAIT1();
        } else {
            CP_WAIT0();
        }
        __syncthreads();

        const uint32_t sb = sbase + stage * G_STAGE;
        const uint32_t abase0 = sb + (uint32_t)((wm * 64 + a_rowlane) * 128);
        const uint32_t bbase0 = sb + G_TILE + (uint32_t)((wn * 32 + b_rowlane) * 128);

        #pragma unroll
        for (int ks = 0; ks < 4; ks++) {
            const uint32_t abase = abase0 + (uint32_t)(((ks * 2 + a_csel) ^ sw_lane) << 4);
            const uint32_t bbase = bbase0 + (uint32_t)(((ks * 2 + b_csel) ^ sw_lane) << 4);

            uint32_t a[4][4], bb[2][4];
            #pragma unroll
            for (int tm = 0; tm < 4; tm++) LDSM4(a[tm], abase + tm * 2048);
            #pragma unroll
            for (int tg = 0; tg < 2; tg++) LDSM4(bb[tg], bbase + tg * 2048);

            #pragma unroll
            for (int tm = 0; tm < 4; tm++) {
                #pragma unroll
                for (int tg = 0; tg < 2; tg++) {
                    MMA16816(acc[tm][tg * 2 + 0], a[tm], bb[tg][0], bb[tg][1]);
                    MMA16816(acc[tm][tg * 2 + 1], a[tm], bb[tg][2], bb[tg][3]);
                }
            }
        }
        __syncthreads();
        if (++stage == 3) stage = 0;
    }

    const int erow = (lid >> 2);
    const int ecol = (lid & 3) * 2;
    #pragma unroll
    for (int tm = 0; tm < 4; tm++) {
        #pragma unroll
        for (int tg = 0; tg < 4; tg++) {
            int row = m0 + wm * 64 + tm * 16 + erow;
            int col = n0 + wn * 32 + tg * 8 + ecol;
            if (HALF_OUT) {
                *(uint32_t*)(Ch + (size_t)row * N + col) =
                    packh2(acc[tm][tg][0], acc[tm][tg][1]);
                *(uint32_t*)(Ch + (size_t)(row + 8) * N + col) =
                    packh2(acc[tm][tg][2], acc[tm][tg][3]);
            } else {
                *(float2*)(C + (size_t)row * N + col) =
                    make_float2(acc[tm][tg][0], acc[tm][tg][1]);
                *(float2*)(C + (size_t)(row + 8) * N + col) =
                    make_float2(acc[tm][tg][2], acc[tm][tg][3]);
            }
        }
    }
}

// ---------------------------------------------------------------------------
// HMMA flash attention (causal), fp16: S = Q K^T, O += P V (single terms).
// 128 q-rows/CTA, 8 warps (16 rows each), K-tile 64, 3-stage cp.async.
// Smem: Q 128x144B + 3 stages x (K,V) 64x144B = 72KB -> 2 CTA/SM.
// ---------------------------------------------------------------------------
#define AQ    0
#define AKV0  (128 * 144)              /* 18432 */
#define KV_STAGE (2 * 64 * 144)        /* 18432 */
#define A_VH (64 * 144)
#define ATTN_SMEM (AKV0 + 3 * KV_STAGE) /* 73728 */

__device__ __forceinline__ void attn_load_kv(
    const __half* __restrict__ qkv, uint32_t dst, int grow0, int kcol, int tid)
{
    #pragma unroll
    for (int u = 0; u < 4; u++) {
        int piece = u >> 1;                       // 0:K 1:V
        int r = (u & 1) * 32 + (tid >> 3);
        int c = tid & 7;
        const __half* g = qkv + (size_t)(grow0 + r) * 3072 + kcol + piece * D_MODEL + c * 8;
        CP_ASYNC16(dst + piece * (64 * 144) + r * 144 + c * 16, g);
    }
    CP_COMMIT();
}

__global__ void __launch_bounds__(256, 2) attn_hmma_kernel(
    const __half* __restrict__ qkv, __half* __restrict__ ctx16)
{
    extern __shared__ char smem[];
    const uint32_t sbase = smem_u32(smem);
    const int tid = threadIdx.x;
    const int lid = tid & 31;
    const int wm  = tid >> 5;

    const int qb = (int)gridDim.x - 1 - (int)blockIdx.x;  // big tiles first
    const int bh = blockIdx.y;
    const int b  = bh >> 4;
    const int h  = bh & 15;
    const int q0 = qb * 128;
    const int nkt = qb * 2 + 2;

    const int qcol = h * D_K;
    const int browQ = b * SEQ + q0;
    const int kcol = D_MODEL + qcol;

    // --- Q loads (group 0)
    #pragma unroll
    for (int u = 0; u < 4; u++) {
        int r = u * 32 + (tid >> 3);
        int c = tid & 7;
        CP_ASYNC16(sbase + AQ + r * 144 + c * 16,
                   qkv + (size_t)(browQ + r) * 3072 + qcol + c * 8);
    }
    CP_COMMIT();
    // --- KV tiles 0,1 (groups 1,2)
    attn_load_kv(qkv, sbase + AKV0, b * SEQ, kcol, tid);
    if (nkt > 1)
        attn_load_kv(qkv, sbase + AKV0 + KV_STAGE, b * SEQ + 64, kcol, tid);
    else
        CP_COMMIT();  // keep group accounting uniform

    CP_WAIT2();            // Q ready
    __syncthreads();

    // preload Q A-fragments (4 k-steps)
    const uint32_t q_addr = sbase + AQ + (uint32_t)((wm * 16 + (lid & 15)) * 144)
                            + (uint32_t)((lid >> 4) * 16);
    uint32_t aQ[4][4];
    #pragma unroll
    for (int ks = 0; ks < 4; ks++) LDSM4(aQ[ks], q_addr + ks * 32);

    // B-frag lane constants
    const int b_row = ((lid >> 4) << 3) + (lid & 7);
    const int b_cs  = (lid >> 3) & 1;
    const int v_row = ((lid >> 3) & 1) * 8 + (lid & 7);
    const int v_col = (lid >> 4) * 8;

    const int row0 = q0 + wm * 16 + (lid >> 2);
    const int row1 = row0 + 8;

    float O[8][4];
    #pragma unroll
    for (int t = 0; t < 8; t++)
        #pragma unroll
        for (int k = 0; k < 4; k++) O[t][k] = 0.f;
    float m0r = -1e30f, m1r = -1e30f, l0r = 0.f, l1r = 0.f;

    int stage = 0;
    for (int kt = 0; kt < nkt; kt++) {
        if (kt + 2 < nkt) {
            int ps = stage + 2; if (ps >= 3) ps -= 3;
            attn_load_kv(qkv, sbase + AKV0 + ps * KV_STAGE,
                         b * SEQ + (kt + 2) * 64, kcol, tid);
            CP_WAIT2();
        } else if (kt == nkt - 2) {
            CP_WAIT1();
        } else {
            CP_WAIT0();
        }
        __syncthreads();

        const uint32_t stg = sbase + AKV0 + stage * KV_STAGE;

        // ---- S = Q K^T
        float S[8][4];
        #pragma unroll
        for (int t = 0; t < 8; t++)
            #pragma unroll
            for (int k = 0; k < 4; k++) S[t][k] = 0.f;

        #pragma unroll
        for (int ks = 0; ks < 4; ks++) {
            const uint32_t kof = (uint32_t)((ks * 2 + b_cs) * 16);
            #pragma unroll
            for (int g = 0; g < 4; g++) {
                uint32_t kh[4];
                LDSM4(kh, stg + (uint32_t)((g * 16 + b_row) * 144) + kof);
                MMA16816(S[2 * g + 0], aQ[ks], kh[0], kh[1]);
                MMA16816(S[2 * g + 1], aQ[ks], kh[2], kh[3]);
            }
        }

        // ---- scale + causal mask + row max
        const int ktbase = kt * 64;
        const bool need_mask = (ktbase + 63) > (q0 + wm * 16);
        float vmax0 = -1e30f, vmax1 = -1e30f;
        #pragma unroll
        for (int t = 0; t < 8; t++) {
            float s0 = S[t][0] * SCALE, s1 = S[t][1] * SCALE;
            float s2 = S[t][2] * SCALE, s3 = S[t][3] * SCALE;
            if (need_mask) {
                int c0 = ktbase + t * 8 + (lid & 3) * 2;
                if (c0     > row0) s0 = -1e9f;
                if (c0 + 1 > row0) s1 = -1e9f;
                if (c0     > row1) s2 = -1e9f;
                if (c0 + 1 > row1) s3 = -1e9f;
            }
            S[t][0] = s0; S[t][1] = s1; S[t][2] = s2; S[t][3] = s3;
            vmax0 = fmaxf(vmax0, fmaxf(s0, s1));
            vmax1 = fmaxf(vmax1, fmaxf(s2, s3));
        }
        vmax0 = fmaxf(vmax0, __shfl_xor_sync(0xffffffffu, vmax0, 1));
        vmax0 = fmaxf(vmax0, __shfl_xor_sync(0xffffffffu, vmax0, 2));
        vmax1 = fmaxf(vmax1, __shfl_xor_sync(0xffffffffu, vmax1, 1));
        vmax1 = fmaxf(vmax1, __shfl_xor_sync(0xffffffffu, vmax1, 2));

        const float mn0 = fmaxf(m0r, vmax0);
        const float mn1 = fmaxf(m1r, vmax1);
        const float a0 = __expf(m0r - mn0);
        const float a1 = __expf(m1r - mn1);
        m0r = mn0; m1r = mn1;

        float ps0 = 0.f, ps1 = 0.f;
        #pragma unroll
        for (int t = 0; t < 8; t++) {
            S[t][0] = __expf(S[t][0] - mn0);
            S[t][1] = __expf(S[t][1] - mn0);
            S[t][2] = __expf(S[t][2] - mn1);
            S[t][3] = __expf(S[t][3] - mn1);
            ps0 += S[t][0] + S[t][1];
            ps1 += S[t][2] + S[t][3];
        }
        ps0 += __shfl_xor_sync(0xffffffffu, ps0, 1);
        ps0 += __shfl_xor_sync(0xffffffffu, ps0, 2);
        ps1 += __shfl_xor_sync(0xffffffffu, ps1, 1);
        ps1 += __shfl_xor_sync(0xffffffffu, ps1, 2);
        l0r = l0r * a0 + ps0;
        l1r = l1r * a1 + ps1;

        #pragma unroll
        for (int t = 0; t < 8; t++) {
            O[t][0] *= a0; O[t][1] *= a0;
            O[t][2] *= a1; O[t][3] *= a1;
        }

        // ---- P fragments (fp16, C->A layout in registers)
        uint32_t aP[4][4];
        #pragma unroll
        for (int ks = 0; ks < 4; ks++) {
            aP[ks][0] = packh2(S[2 * ks][0],     S[2 * ks][1]);
            aP[ks][1] = packh2(S[2 * ks][2],     S[2 * ks][3]);
            aP[ks][2] = packh2(S[2 * ks + 1][0], S[2 * ks + 1][1]);
            aP[ks][3] = packh2(S[2 * ks + 1][2], S[2 * ks + 1][3]);
        }

        // ---- O += P V, V^T via ldmatrix.trans
        #pragma unroll
        for (int ks = 0; ks < 4; ks++) {
            #pragma unroll
            for (int g = 0; g < 4; g++) {
                uint32_t vh[4];
                LDSM4T(vh, stg + A_VH + (uint32_t)((ks * 16 + v_row) * 144)
                           + (uint32_t)((v_col + g * 16) * 2));
                MMA16816(O[2 * g + 0], aP[ks], vh[0], vh[1]);
                MMA16816(O[2 * g + 1], aP[ks], vh[2], vh[3]);
            }
        }
        __syncthreads();
        if (++stage == 3) stage = 0;
    }

    // ---- epilogue: normalize, fp16 pack, store ctx16 [4096,1024]
    const float inv0 = 1.f / l0r;
    const float inv1 = 1.f / l1r;
    const int gr0 = b * SEQ + row0;
    const int gr1 = b * SEQ + row1;
    #pragma unroll
    for (int t = 0; t < 8; t++) {
        int col = qcol + t * 8 + (lid & 3) * 2;
        *(uint32_t*)(ctx16 + (size_t)gr0 * D_MODEL + col) =
            packh2(O[t][0] * inv0, O[t][1] * inv0);
        *(uint32_t*)(ctx16 + (size_t)gr1 * D_MODEL + col) =
            packh2(O[t][2] * inv1, O[t][3] * inv1);
    }
}

// ---------------------------------------------------------------------------
extern "C" void kernel_launch(void* const* d_in, const int* in_sizes, int n_in,
                              void* d_out, int out_size)
{
    const float* query = (const float*)d_in[0];
    const float* w_qkv = (const float*)d_in[4];
    const float* w_o   = (const float*)d_in[5];
    float* out = (float*)d_out;

    __half *A16, *ctx16, *QKV, *W1, *W2;
    cudaGetSymbolAddress((void**)&A16,   g_A16);
    cudaGetSymbolAddress((void**)&ctx16, g_ctx16);
    cudaGetSymbolAddress((void**)&QKV,   g_QKV);
    cudaGetSymbolAddress((void**)&W1,    g_W1);
    cudaGetSymbolAddress((void**)&W2,    g_W2);

    cudaFuncSetAttribute(gemm_hmma_kernel<true>,
                         cudaFuncAttributeMaxDynamicSharedMemorySize, GEMM_SMEM);
    cudaFuncSetAttribute(gemm_hmma_kernel<false>,
                         cudaFuncAttributeMaxDynamicSharedMemorySize, GEMM_SMEM);
    cudaFuncSetAttribute(attn_hmma_kernel,
                         cudaFuncAttributeMaxDynamicSharedMemorySize, ATTN_SMEM);

    // Prep
    {
        dim3 blk(32, 8);
        transpose_half_kernel<<<dim3(3 * D_MODEL / 32, D_MODEL / 32), blk>>>(
            w_qkv, W1, D_MODEL, 3 * D_MODEL);
        transpose_half_kernel<<<dim3(D_MODEL / 32, D_MODEL / 32), blk>>>(
            w_o, W2, D_MODEL, D_MODEL);
        int n4 = M_ROWS * D_MODEL / 4;
        tohalf_kernel<<<(n4 + 255) / 256, 256>>>(query, A16, n4);
    }

    // 1) qkv = query @ w_qkv -> fp16
    gemm_hmma_kernel<true><<<dim3(3 * D_MODEL / 128, M_ROWS / 128), 256, GEMM_SMEM>>>(
        A16, W1, nullptr, QKV, M_ROWS, 3 * D_MODEL, D_MODEL);

    // 2) causal flash attention -> ctx fp16
    attn_hmma_kernel<<<dim3(SEQ / 128, BATCH * N_HEADS), 256, ATTN_SMEM>>>(
        QKV, ctx16);

    // 3) out = ctx @ w_o -> fp32
    gemm_hmma_kernel<false><<<dim3(D_MODEL / 128, M_ROWS / 128), 256, GEMM_SMEM>>>(
        ctx16, W2, out, nullptr, M_ROWS, D_MODEL, D_MODEL);
}